// round 4
// baseline (speedup 1.0000x reference)
#include <cuda_runtime.h>
#include <cuda_bf16.h>
#include <cstdint>
#include <math.h>

// Problem constants
#define S_LEN 2048
#define HID 2048
#define NH 16
#define NKV 4
#define HD 128
#define QKV_OUT 3072   // (16 + 2*4) * 128
#define Q_SZ 2048      // 16*128
#define KV_SZ 512      // 4*128
#define SCALE_Q 0.08838834764831845f  // 128^-0.5

// ---------------- scratch (static device arrays; no allocation) -------------
__device__ float g_qkv[S_LEN * QKV_OUT];
__device__ float g_q[S_LEN * NH * HD];
__device__ float g_k[S_LEN * NKV * HD];
__device__ float g_v[S_LEN * NKV * HD];
__device__ float g_attn[S_LEN * NH * HD];

// =================== helpers =================================================
__device__ __forceinline__ float tf32_rna(float x) {
    uint32_t r;
    asm("cvt.rna.tf32.f32 %0, %1;" : "=r"(r) : "f"(x));
    return __uint_as_float(r);
}
__device__ __forceinline__ void split4(float4 v, float4& hi, float4& lo) {
    hi.x = tf32_rna(v.x); lo.x = tf32_rna(v.x - hi.x);
    hi.y = tf32_rna(v.y); lo.y = tf32_rna(v.y - hi.y);
    hi.z = tf32_rna(v.z); lo.z = tf32_rna(v.z - hi.z);
    hi.w = tf32_rna(v.w); lo.w = tf32_rna(v.w - hi.w);
}

#define MMA_TF32(d, a, b) \
    asm volatile( \
        "mma.sync.aligned.m16n8k8.row.col.f32.tf32.tf32.f32 " \
        "{%0,%1,%2,%3}, {%4,%5,%6,%7}, {%8,%9}, {%0,%1,%2,%3};" \
        : "+f"((d)[0]), "+f"((d)[1]), "+f"((d)[2]), "+f"((d)[3]) \
        : "r"((a)[0]), "r"((a)[1]), "r"((a)[2]), "r"((a)[3]), \
          "r"((b)[0]), "r"((b)[1]))

// =================== 3xTF32 mma.sync GEMM ====================================
// C[M,N] = A[M,K] @ B[N,K]^T + bias[N], fp32 in/out.
// CTA tile 128x128, 256 threads (8 warps, 4x2), warp tile 32x64, K-chunk 32.
// smem per stage: Ahi|Alo|Bhi|Blo, each [128][36] floats (skewed, conflict-free)
#define GPAD 36
#define GBUF (128 * GPAD)                    // floats per buffer = 4608
#define G_STAGE_FLOATS (4 * GBUF)            // 18432 floats
#define G_SMEM_BYTES (2 * G_STAGE_FLOATS * 4) // 147456 B

__global__ void __launch_bounds__(256, 1)
gemm_tc(const float* __restrict__ A, const float* __restrict__ B,
        const float* __restrict__ bias, float* __restrict__ C,
        int N, int K) {
    extern __shared__ float smem[];
    const int t = threadIdx.x;
    const int lane = t & 31, wid = t >> 5;
    const int g = lane >> 2, tg = lane & 3;
    const int wm = (wid & 3) * 32;   // warp m offset in tile
    const int wn = (wid >> 2) * 64;  // warp n offset in tile
    const int m0 = blockIdx.y << 7, n0 = blockIdx.x << 7;
    const int nch = K >> 5;

    float d[2][8][4];
#pragma unroll
    for (int i = 0; i < 2; i++)
#pragma unroll
        for (int j = 0; j < 8; j++)
#pragma unroll
            for (int q = 0; q < 4; q++) d[i][j][q] = 0.f;

    float4 ra[4], rb[4];

#define G_LOADC(c) do { \
    _Pragma("unroll") \
    for (int i = 0; i < 4; i++) { \
        int idx = t + (i << 8); int r = idx >> 3, q = idx & 7; \
        ra[i] = *(const float4*)(A + (size_t)(m0 + r) * K + ((c) << 5) + (q << 2)); \
        rb[i] = *(const float4*)(B + (size_t)(n0 + r) * K + ((c) << 5) + (q << 2)); \
    } } while (0)

#define G_STSC(st) do { \
    float* Ah = smem + (st) * G_STAGE_FLOATS; \
    float* Al = Ah + GBUF; \
    float* Bh = Al + GBUF; \
    float* Bl = Bh + GBUF; \
    _Pragma("unroll") \
    for (int i = 0; i < 4; i++) { \
        int idx = t + (i << 8); int r = idx >> 3, q = idx & 7; \
        int off = r * GPAD + (q << 2); \
        float4 hi, lo; \
        split4(ra[i], hi, lo); \
        *(float4*)(Ah + off) = hi; \
        *(float4*)(Al + off) = lo; \
        split4(rb[i], hi, lo); \
        *(float4*)(Bh + off) = hi; \
        *(float4*)(Bl + off) = lo; \
    } } while (0)

    G_LOADC(0);
    G_STSC(0);
    __syncthreads();

    for (int c = 0; c < nch; c++) {
        const int st = c & 1;
        if (c + 1 < nch) G_LOADC(c + 1);

        const uint32_t* Ah = (const uint32_t*)(smem + st * G_STAGE_FLOATS);
        const uint32_t* Al = Ah + GBUF;
        const uint32_t* Bh = Al + GBUF;
        const uint32_t* Bl = Bh + GBUF;

#pragma unroll
        for (int ks = 0; ks < 4; ks++) {
            const int kb = ks * 8;
            uint32_t ah[2][4], al[2][4];
#pragma unroll
            for (int i = 0; i < 2; i++) {
                int r0 = wm + i * 16 + g;
                ah[i][0] = Ah[r0 * GPAD + kb + tg];
                ah[i][1] = Ah[(r0 + 8) * GPAD + kb + tg];
                ah[i][2] = Ah[r0 * GPAD + kb + tg + 4];
                ah[i][3] = Ah[(r0 + 8) * GPAD + kb + tg + 4];
                al[i][0] = Al[r0 * GPAD + kb + tg];
                al[i][1] = Al[(r0 + 8) * GPAD + kb + tg];
                al[i][2] = Al[r0 * GPAD + kb + tg + 4];
                al[i][3] = Al[(r0 + 8) * GPAD + kb + tg + 4];
            }
            uint32_t bh[8][2], bl[8][2];
#pragma unroll
            for (int j = 0; j < 8; j++) {
                int n = wn + j * 8 + g;
                bh[j][0] = Bh[n * GPAD + kb + tg];
                bh[j][1] = Bh[n * GPAD + kb + tg + 4];
                bl[j][0] = Bl[n * GPAD + kb + tg];
                bl[j][1] = Bl[n * GPAD + kb + tg + 4];
            }
#pragma unroll
            for (int i = 0; i < 2; i++)
#pragma unroll
                for (int j = 0; j < 8; j++) {
                    MMA_TF32(d[i][j], ah[i], bh[j]);
                    MMA_TF32(d[i][j], ah[i], bl[j]);
                    MMA_TF32(d[i][j], al[i], bh[j]);
                }
        }

        if (c + 1 < nch) {
            __syncthreads();
            G_STSC(st ^ 1);
            __syncthreads();
        }
    }

    // epilogue: bias + store (float2 per fragment half)
#pragma unroll
    for (int i = 0; i < 2; i++) {
        int r = m0 + wm + i * 16 + g;
#pragma unroll
        for (int j = 0; j < 8; j++) {
            int cix = n0 + wn + j * 8 + tg * 2;
            float2 b2 = *(const float2*)(bias + cix);
            float2 v0, v1;
            v0.x = d[i][j][0] + b2.x; v0.y = d[i][j][1] + b2.y;
            v1.x = d[i][j][2] + b2.x; v1.y = d[i][j][3] + b2.y;
            *(float2*)(C + (size_t)r * N + cix) = v0;
            *(float2*)(C + (size_t)(r + 8) * N + cix) = v1;
        }
    }
#undef G_LOADC
#undef G_STSC
}

// ---------------- copy caches into scratch ----------------------------------
__global__ void copy_caches(const float* __restrict__ kc, const float* __restrict__ vc) {
    int n = S_LEN * NKV * HD;
    for (int i = blockIdx.x * blockDim.x + threadIdx.x; i < n; i += gridDim.x * blockDim.x) {
        g_k[i] = kc[i];
        g_v[i] = vc[i];
    }
}

// ---------------- fused RMSNorm + RoPE + scale + scatter ---------------------
__global__ void norm_rope_scatter(const float* __restrict__ cosb,
                                  const float* __restrict__ sinb,
                                  const float* __restrict__ qw,
                                  const float* __restrict__ kw,
                                  const int* __restrict__ widx) {
    const int s = blockIdx.x;
    const int head = blockIdx.y;
    const int d = threadIdx.x;
    __shared__ float sh[128];
    __shared__ float wsum[4];

    int col;
    if (head < 16)      col = head * HD + d;
    else if (head < 20) col = Q_SZ + (head - 16) * HD + d;
    else                col = Q_SZ + KV_SZ + (head - 20) * HD + d;

    float x = g_qkv[(size_t)s * QKV_OUT + col];

    if (head >= 20) {
        int idx = widx[s];
        g_v[((size_t)idx * NKV + (head - 20)) * HD + d] = x;
        return;
    }

    float sq = x * x;
#pragma unroll
    for (int m = 16; m; m >>= 1) sq += __shfl_xor_sync(0xffffffffu, sq, m);
    if ((d & 31) == 0) wsum[d >> 5] = sq;
    __syncthreads();
    float ms = (wsum[0] + wsum[1] + wsum[2] + wsum[3]) * (1.0f / 128.0f);
    float inv = rsqrtf(ms + 1e-6f);
    const float* w = (head < 16) ? qw : kw;
    float y = x * inv * w[d];
    sh[d] = y;
    __syncthreads();

    if (d < 64) {
        float c = cosb[s * 64 + d], sn = sinb[s * 64 + d];
        float x1 = sh[d], x2 = sh[d + 64];
        float y1 = x1 * c - x2 * sn;
        float y2 = x1 * sn + x2 * c;
        if (head < 16) {
            float* dst = g_q + ((size_t)s * NH + head) * HD;
            dst[d] = y1 * SCALE_Q;
            dst[d + 64] = y2 * SCALE_Q;
        } else {
            int idx = widx[s];
            float* dst = g_k + ((size_t)idx * NKV + (head - 16)) * HD;
            dst[d] = y1;
            dst[d + 64] = y2;
        }
    }
}

// ---------------- flash attention (unchanged) --------------------------------
#define ATTN_SMEM ((128 * 65 * 2 + 64 * 128 + 64 * 65) * 4)
__global__ void attn_kernel(const float* __restrict__ mask) {
    extern __shared__ float sm[];
    float* Qt = sm;
    float* Kt = Qt + 128 * 65;
    float* Vs = Kt + 128 * 65;
    float* Ps = Vs + 64 * 128;

    const int t = threadIdx.x;
    const int tx = t & 15, ty = t >> 4;
    const int q0 = blockIdx.x * 64;
    const int h = blockIdx.y;
    const int kvh = h >> 2;

#pragma unroll
    for (int i = 0; i < 32; i++) {
        int idx = t + i * 256;
        int d = idx & 127, r = idx >> 7;
        Qt[d * 65 + r] = g_q[((size_t)(q0 + r) * NH + h) * HD + d];
    }

    float o[4][8];
    float mrow[4], lrow[4];
#pragma unroll
    for (int i = 0; i < 4; i++) {
        mrow[i] = -1e30f; lrow[i] = 0.f;
#pragma unroll
        for (int j = 0; j < 8; j++) o[i][j] = 0.f;
    }

    const int ktiles = blockIdx.x + 1;
    for (int kt = 0; kt < ktiles; kt++) {
        const int k0 = kt * 64;
        __syncthreads();
#pragma unroll
        for (int i = 0; i < 32; i++) {
            int idx = t + i * 256;
            int d = idx & 127, c = idx >> 7;
            Kt[d * 65 + c] = g_k[((size_t)(k0 + c) * NKV + kvh) * HD + d];
            Vs[c * 128 + d] = g_v[((size_t)(k0 + c) * NKV + kvh) * HD + d];
        }
        __syncthreads();

        float sc[4][4];
#pragma unroll
        for (int i = 0; i < 4; i++)
#pragma unroll
            for (int j = 0; j < 4; j++) sc[i][j] = 0.f;
#pragma unroll 8
        for (int d = 0; d < 128; d++) {
            float qv[4], kv[4];
#pragma unroll
            for (int i = 0; i < 4; i++) qv[i] = Qt[d * 65 + ty + 16 * i];
#pragma unroll
            for (int j = 0; j < 4; j++) kv[j] = Kt[d * 65 + tx + 16 * j];
#pragma unroll
            for (int i = 0; i < 4; i++)
#pragma unroll
                for (int j = 0; j < 4; j++) sc[i][j] += qv[i] * kv[j];
        }

#pragma unroll
        for (int i = 0; i < 4; i++) {
            int r = q0 + ty + 16 * i;
            float tmax = -1e30f;
#pragma unroll
            for (int j = 0; j < 4; j++) {
                int c = k0 + tx + 16 * j;
                sc[i][j] += mask[(size_t)r * S_LEN + c];
                tmax = fmaxf(tmax, sc[i][j]);
            }
#pragma unroll
            for (int mm = 8; mm; mm >>= 1)
                tmax = fmaxf(tmax, __shfl_xor_sync(0xffffffffu, tmax, mm));
            float mnew = fmaxf(mrow[i], tmax);
            float scalef = __expf(mrow[i] - mnew);
            mrow[i] = mnew;
            float tsum = 0.f;
#pragma unroll
            for (int j = 0; j < 4; j++) {
                float p = __expf(sc[i][j] - mnew);
                sc[i][j] = p;
                tsum += p;
            }
#pragma unroll
            for (int mm = 8; mm; mm >>= 1)
                tsum += __shfl_xor_sync(0xffffffffu, tsum, mm);
            lrow[i] = lrow[i] * scalef + tsum;
#pragma unroll
            for (int j = 0; j < 8; j++) o[i][j] *= scalef;
#pragma unroll
            for (int j = 0; j < 4; j++)
                Ps[(ty + 16 * i) * 65 + tx + 16 * j] = sc[i][j];
        }
        __syncthreads();

#pragma unroll 4
        for (int k = 0; k < 64; k++) {
            float pv[4], vv[8];
#pragma unroll
            for (int i = 0; i < 4; i++) pv[i] = Ps[(ty + 16 * i) * 65 + k];
#pragma unroll
            for (int j = 0; j < 8; j++) vv[j] = Vs[k * 128 + tx + 16 * j];
#pragma unroll
            for (int i = 0; i < 4; i++)
#pragma unroll
                for (int j = 0; j < 8; j++) o[i][j] += pv[i] * vv[j];
        }
    }

#pragma unroll
    for (int i = 0; i < 4; i++) {
        float invl = 1.0f / lrow[i];
        int r = q0 + ty + 16 * i;
#pragma unroll
        for (int j = 0; j < 8; j++)
            g_attn[(size_t)r * (NH * HD) + h * HD + tx + 16 * j] = o[i][j] * invl;
    }
}

// ---------------- launch -----------------------------------------------------
extern "C" void kernel_launch(void* const* d_in, const int* in_sizes, int n_in,
                              void* d_out, int out_size) {
    const float* hidden = (const float*)d_in[0];
    const float* cosb   = (const float*)d_in[1];
    const float* sinb   = (const float*)d_in[2];
    const float* kcache = (const float*)d_in[3];
    const float* vcache = (const float*)d_in[4];
    const float* mask   = (const float*)d_in[5];
    const float* wqkv   = (const float*)d_in[6];
    const float* bqkv   = (const float*)d_in[7];
    const float* wo     = (const float*)d_in[8];
    const float* bo     = (const float*)d_in[9];
    const float* qw     = (const float*)d_in[10];
    const float* kw     = (const float*)d_in[11];
    const int*   widx   = (const int*)d_in[12];
    float* out = (float*)d_out;

    float *p_qkv, *p_attn;
    cudaGetSymbolAddress((void**)&p_qkv, g_qkv);
    cudaGetSymbolAddress((void**)&p_attn, g_attn);

    static bool attr_set = false;
    if (!attr_set) {
        cudaFuncSetAttribute(attn_kernel, cudaFuncAttributeMaxDynamicSharedMemorySize, ATTN_SMEM);
        cudaFuncSetAttribute(gemm_tc, cudaFuncAttributeMaxDynamicSharedMemorySize, G_SMEM_BYTES);
        attr_set = true;
    }

    // 1. QKV GEMM: [2048,3072] = hidden @ wqkv^T + bqkv  (3xTF32 mma.sync)
    gemm_tc<<<dim3(QKV_OUT / 128, S_LEN / 128), 256, G_SMEM_BYTES>>>(
        hidden, wqkv, bqkv, p_qkv, QKV_OUT, HID);

    // 2. caches -> scratch
    copy_caches<<<256, 256>>>(kcache, vcache);

    // 3. RMSNorm + RoPE + scale + scatter
    norm_rope_scatter<<<dim3(S_LEN, 24), 128>>>(cosb, sinb, qw, kw, widx);

    // 4. flash attention
    attn_kernel<<<dim3(S_LEN / 64, NH), 256, ATTN_SMEM>>>(mask);

    // 5. output projection: [2048,2048] = attn @ wo^T + bo  (3xTF32 mma.sync)
    gemm_tc<<<dim3(HID / 128, S_LEN / 128), 256, G_SMEM_BYTES>>>(
        p_attn, wo, bo, out, HID, NH * HD);
}

// round 5
// speedup vs baseline: 1.6489x; 1.6489x over previous
#include <cuda_runtime.h>
#include <cuda_bf16.h>
#include <cstdint>
#include <math.h>

// Problem constants
#define S_LEN 2048
#define HID 2048
#define NH 16
#define NKV 4
#define HD 128
#define QKV_OUT 3072   // (16 + 2*4) * 128
#define Q_SZ 2048      // 16*128
#define KV_SZ 512      // 4*128
#define SCALE_Q 0.08838834764831845f  // 128^-0.5

// ---------------- scratch (static device arrays; no allocation) -------------
__device__ float g_qkv[S_LEN * QKV_OUT];
__device__ float g_q[S_LEN * NH * HD];
__device__ float g_k[S_LEN * NKV * HD];
__device__ float g_v[S_LEN * NKV * HD];
__device__ float g_attn[S_LEN * NH * HD];

// =================== helpers =================================================
__device__ __forceinline__ uint32_t smem_u32(const void* p) {
    return (uint32_t)__cvta_generic_to_shared(p);
}
__device__ __forceinline__ float tf32_rna(float x) {
    uint32_t r;
    asm("cvt.rna.tf32.f32 %0, %1;" : "=r"(r) : "f"(x));
    return __uint_as_float(r);
}
__device__ __forceinline__ void split4(float4 v, float4& hi, float4& lo) {
    hi.x = tf32_rna(v.x); lo.x = tf32_rna(v.x - hi.x);
    hi.y = tf32_rna(v.y); lo.y = tf32_rna(v.y - hi.y);
    hi.z = tf32_rna(v.z); lo.z = tf32_rna(v.z - hi.z);
    hi.w = tf32_rna(v.w); lo.w = tf32_rna(v.w - hi.w);
}

#define MMA_TF32(d, a, b) \
    asm volatile( \
        "mma.sync.aligned.m16n8k8.row.col.f32.tf32.tf32.f32 " \
        "{%0,%1,%2,%3}, {%4,%5,%6,%7}, {%8,%9}, {%0,%1,%2,%3};" \
        : "+f"((d)[0]), "+f"((d)[1]), "+f"((d)[2]), "+f"((d)[3]) \
        : "r"((a)[0]), "r"((a)[1]), "r"((a)[2]), "r"((a)[3]), \
          "r"((b)[0]), "r"((b)[1]))

#define LDSM4(r, addr) \
    asm volatile("ldmatrix.sync.aligned.m8n8.x4.shared.b16 {%0,%1,%2,%3}, [%4];" \
        : "=r"((r)[0]), "=r"((r)[1]), "=r"((r)[2]), "=r"((r)[3]) : "r"(addr))

// =================== 3xTF32 mma.sync GEMM (ldmatrix fragments) ==============
// C[M,N] = A[M,K] @ B[N,K]^T + bias[N], fp32 in/out.
// CTA tile 128x128, 256 threads (8 warps, 4x2), warp tile 32x64, K-chunk 32.
#define GPAD 36
#define GBUF (128 * GPAD)                     // floats per buffer = 4608
#define GBUF_B (GBUF * 4)                     // bytes = 18432
#define G_STAGE_FLOATS (4 * GBUF)             // 18432 floats
#define G_STG_B (G_STAGE_FLOATS * 4)          // 73728 bytes
#define G_SMEM_BYTES (2 * G_STG_B)            // 147456 B

__global__ void __launch_bounds__(256, 1)
gemm_tc(const float* __restrict__ A, const float* __restrict__ B,
        const float* __restrict__ bias, float* __restrict__ C,
        int N, int K) {
    extern __shared__ float smem[];
    const int t = threadIdx.x;
    const int lane = t & 31, wid = t >> 5;
    const int g = lane >> 2, tg = lane & 3;
    const int wm = (wid & 3) * 32;   // warp m offset in tile
    const int wn = (wid >> 2) * 64;  // warp n offset in tile
    const int m0 = blockIdx.y << 7, n0 = blockIdx.x << 7;
    const int nch = K >> 5;

    // per-lane ldmatrix byte offsets (within a buffer)
    const int l15 = lane & 15;
    const int csel = (lane >> 4) << 2;
    const uint32_t sbase = smem_u32(smem);
    const uint32_t offA0 = ((wm + l15) * GPAD + csel) * 4;
    const uint32_t offA1 = ((wm + 16 + l15) * GPAD + csel) * 4;
    uint32_t offB[4];
#pragma unroll
    for (int jp = 0; jp < 4; jp++) offB[jp] = ((wn + jp * 16 + l15) * GPAD + csel) * 4;

    float d[2][8][4];
#pragma unroll
    for (int i = 0; i < 2; i++)
#pragma unroll
        for (int j = 0; j < 8; j++)
#pragma unroll
            for (int q = 0; q < 4; q++) d[i][j][q] = 0.f;

    float4 ra[4], rb[4];

#define G_LOADC(c) do { \
    _Pragma("unroll") \
    for (int i = 0; i < 4; i++) { \
        int idx = t + (i << 8); int r = idx >> 3, q = idx & 7; \
        ra[i] = *(const float4*)(A + (size_t)(m0 + r) * K + ((c) << 5) + (q << 2)); \
        rb[i] = *(const float4*)(B + (size_t)(n0 + r) * K + ((c) << 5) + (q << 2)); \
    } } while (0)

#define G_STSC(st) do { \
    float* Ah = smem + (st) * G_STAGE_FLOATS; \
    float* Al = Ah + GBUF; \
    float* Bh = Al + GBUF; \
    float* Bl = Bh + GBUF; \
    _Pragma("unroll") \
    for (int i = 0; i < 4; i++) { \
        int idx = t + (i << 8); int r = idx >> 3, q = idx & 7; \
        int off = r * GPAD + (q << 2); \
        float4 hi, lo; \
        split4(ra[i], hi, lo); \
        *(float4*)(Ah + off) = hi; \
        *(float4*)(Al + off) = lo; \
        split4(rb[i], hi, lo); \
        *(float4*)(Bh + off) = hi; \
        *(float4*)(Bl + off) = lo; \
    } } while (0)

    G_LOADC(0);
    G_STSC(0);
    __syncthreads();

    for (int c = 0; c < nch; c++) {
        const int st = c & 1;
        if (c + 1 < nch) G_LOADC(c + 1);

        const uint32_t aH = sbase + st * G_STG_B;
        const uint32_t aL = aH + GBUF_B;
        const uint32_t bH = aH + 2 * GBUF_B;
        const uint32_t bL = aH + 3 * GBUF_B;

#pragma unroll
        for (int ks = 0; ks < 4; ks++) {
            const uint32_t ko = ks * 32;
            uint32_t ah0[4], ah1[4], al0[4], al1[4];
            LDSM4(ah0, aH + offA0 + ko);
            LDSM4(ah1, aH + offA1 + ko);
            LDSM4(al0, aL + offA0 + ko);
            LDSM4(al1, aL + offA1 + ko);
#pragma unroll
            for (int jp = 0; jp < 4; jp++) {
                uint32_t bh[4], bl[4];
                LDSM4(bh, bH + offB[jp] + ko);
                LDSM4(bl, bL + offB[jp] + ko);
                uint32_t b0h[2] = {bh[0], bh[2]};
                uint32_t b1h[2] = {bh[1], bh[3]};
                uint32_t b0l[2] = {bl[0], bl[2]};
                uint32_t b1l[2] = {bl[1], bl[3]};
                MMA_TF32(d[0][2 * jp], ah0, b0h);
                MMA_TF32(d[0][2 * jp], ah0, b0l);
                MMA_TF32(d[0][2 * jp], al0, b0h);
                MMA_TF32(d[0][2 * jp + 1], ah0, b1h);
                MMA_TF32(d[0][2 * jp + 1], ah0, b1l);
                MMA_TF32(d[0][2 * jp + 1], al0, b1h);
                MMA_TF32(d[1][2 * jp], ah1, b0h);
                MMA_TF32(d[1][2 * jp], ah1, b0l);
                MMA_TF32(d[1][2 * jp], al1, b0h);
                MMA_TF32(d[1][2 * jp + 1], ah1, b1h);
                MMA_TF32(d[1][2 * jp + 1], ah1, b1l);
                MMA_TF32(d[1][2 * jp + 1], al1, b1h);
            }
        }

        if (c + 1 < nch) {
            __syncthreads();
            G_STSC(st ^ 1);
            __syncthreads();
        }
    }

    // epilogue: bias + store
#pragma unroll
    for (int i = 0; i < 2; i++) {
        int r = m0 + wm + i * 16 + g;
#pragma unroll
        for (int j = 0; j < 8; j++) {
            int cix = n0 + wn + j * 8 + tg * 2;
            float2 b2 = *(const float2*)(bias + cix);
            float2 v0, v1;
            v0.x = d[i][j][0] + b2.x; v0.y = d[i][j][1] + b2.y;
            v1.x = d[i][j][2] + b2.x; v1.y = d[i][j][3] + b2.y;
            *(float2*)(C + (size_t)r * N + cix) = v0;
            *(float2*)(C + (size_t)(r + 8) * N + cix) = v1;
        }
    }
#undef G_LOADC
#undef G_STSC
}

// ---------------- copy caches into scratch ----------------------------------
__global__ void copy_caches(const float* __restrict__ kc, const float* __restrict__ vc) {
    int n = S_LEN * NKV * HD;
    for (int i = blockIdx.x * blockDim.x + threadIdx.x; i < n; i += gridDim.x * blockDim.x) {
        g_k[i] = kc[i];
        g_v[i] = vc[i];
    }
}

// ---------------- fused RMSNorm + RoPE + scale + scatter ---------------------
__global__ void norm_rope_scatter(const float* __restrict__ cosb,
                                  const float* __restrict__ sinb,
                                  const float* __restrict__ qw,
                                  const float* __restrict__ kw,
                                  const int* __restrict__ widx) {
    const int s = blockIdx.x;
    const int head = blockIdx.y;
    const int d = threadIdx.x;
    __shared__ float sh[128];
    __shared__ float wsum[4];

    int col;
    if (head < 16)      col = head * HD + d;
    else if (head < 20) col = Q_SZ + (head - 16) * HD + d;
    else                col = Q_SZ + KV_SZ + (head - 20) * HD + d;

    float x = g_qkv[(size_t)s * QKV_OUT + col];

    if (head >= 20) {
        int idx = widx[s];
        g_v[((size_t)idx * NKV + (head - 20)) * HD + d] = x;
        return;
    }

    float sq = x * x;
#pragma unroll
    for (int m = 16; m; m >>= 1) sq += __shfl_xor_sync(0xffffffffu, sq, m);
    if ((d & 31) == 0) wsum[d >> 5] = sq;
    __syncthreads();
    float ms = (wsum[0] + wsum[1] + wsum[2] + wsum[3]) * (1.0f / 128.0f);
    float inv = rsqrtf(ms + 1e-6f);
    const float* w = (head < 16) ? qw : kw;
    float y = x * inv * w[d];
    sh[d] = y;
    __syncthreads();

    if (d < 64) {
        float c = cosb[s * 64 + d], sn = sinb[s * 64 + d];
        float x1 = sh[d], x2 = sh[d + 64];
        float y1 = x1 * c - x2 * sn;
        float y2 = x1 * sn + x2 * c;
        if (head < 16) {
            float* dst = g_q + ((size_t)s * NH + head) * HD;
            dst[d] = y1 * SCALE_Q;
            dst[d + 64] = y2 * SCALE_Q;
        } else {
            int idx = widx[s];
            float* dst = g_k + ((size_t)idx * NKV + (head - 16)) * HD;
            dst[d] = y1;
            dst[d + 64] = y2;
        }
    }
}

// ---------------- tensor-core flash attention --------------------------------
// 128 threads (4 warps), CTA = 64 q rows of one head. Warp w owns q rows
// [w*16, w*16+16). k-tiles of 64. 3xTF32 for scores and PV. Causal analytic.
// smem buffers (stride 132 floats): Qh Ql Kh Kl Vh Vl, each 64x132.
#define AP 132
#define ABUF (64 * AP)              // 8448 floats
#define ATTN_SMEM2 (6 * ABUF * 4)   // 202752 bytes

__global__ void __launch_bounds__(128, 1) attn_tc() {
    extern __shared__ float sm[];
    float* Qh = sm;
    float* Ql = sm + ABUF;
    float* Kh = sm + 2 * ABUF;
    float* Kl = sm + 3 * ABUF;
    float* Vh = sm + 4 * ABUF;
    float* Vl = sm + 5 * ABUF;

    const int t = threadIdx.x;
    const int lane = t & 31, w = t >> 5;
    const int g = lane >> 2, tg = lane & 3;
    const int qt = gridDim.x - 1 - blockIdx.x;   // heavy CTAs first
    const int q0 = qt * 64;
    const int h = blockIdx.y, kvh = h >> 2;

    // ---- load Q tile, split to tf32 hi/lo ----
#pragma unroll
    for (int i = 0; i < 16; i++) {
        int idx = t + i * 128;
        int r = idx >> 5, c4 = (idx & 31) << 2;
        float4 v = *(const float4*)(g_q + ((size_t)(q0 + r) * NH + h) * HD + c4);
        float4 hi, lo;
        split4(v, hi, lo);
        *(float4*)(Qh + r * AP + c4) = hi;
        *(float4*)(Ql + r * AP + c4) = lo;
    }

    // ldsm base addresses (bytes)
    const int l15 = lane & 15;
    const int csel = (lane >> 4) << 2;
    const uint32_t qbh = smem_u32(Qh) + ((w * 16 + l15) * AP + csel) * 4;
    const uint32_t qbl = smem_u32(Ql) + ((w * 16 + l15) * AP + csel) * 4;
    uint32_t kbh[4], kbl[4];
#pragma unroll
    for (int jp = 0; jp < 4; jp++) {
        kbh[jp] = smem_u32(Kh) + ((jp * 16 + l15) * AP + csel) * 4;
        kbl[jp] = smem_u32(Kl) + ((jp * 16 + l15) * AP + csel) * 4;
    }

    float o[16][4];
#pragma unroll
    for (int dt = 0; dt < 16; dt++)
#pragma unroll
        for (int q = 0; q < 4; q++) o[dt][q] = 0.f;
    float mrow[2] = {-1e30f, -1e30f};
    float lrow[2] = {0.f, 0.f};

    const int nkt = qt + 1;
    for (int kt = 0; kt < nkt; kt++) {
        const int k0 = kt * 64;
        __syncthreads();   // all warps done reading K/V of previous tile
        // ---- load K, V; split; STS ----
        {
            float4 rk[16];
#pragma unroll
            for (int i = 0; i < 16; i++) {
                int idx = t + i * 128;
                int r = idx >> 5, c4 = (idx & 31) << 2;
                rk[i] = *(const float4*)(g_k + ((size_t)(k0 + r) * NKV + kvh) * HD + c4);
            }
#pragma unroll
            for (int i = 0; i < 16; i++) {
                int idx = t + i * 128;
                int r = idx >> 5, c4 = (idx & 31) << 2;
                float4 hi, lo;
                split4(rk[i], hi, lo);
                *(float4*)(Kh + r * AP + c4) = hi;
                *(float4*)(Kl + r * AP + c4) = lo;
            }
#pragma unroll
            for (int i = 0; i < 16; i++) {
                int idx = t + i * 128;
                int r = idx >> 5, c4 = (idx & 31) << 2;
                rk[i] = *(const float4*)(g_v + ((size_t)(k0 + r) * NKV + kvh) * HD + c4);
            }
#pragma unroll
            for (int i = 0; i < 16; i++) {
                int idx = t + i * 128;
                int r = idx >> 5, c4 = (idx & 31) << 2;
                float4 hi, lo;
                split4(rk[i], hi, lo);
                *(float4*)(Vh + r * AP + c4) = hi;
                *(float4*)(Vl + r * AP + c4) = lo;
            }
        }
        __syncthreads();

        // ---- scores S[16q x 64k] per warp: 3xTF32 over d=128 ----
        float s[8][4];
#pragma unroll
        for (int j = 0; j < 8; j++)
#pragma unroll
            for (int q = 0; q < 4; q++) s[j][q] = 0.f;

#pragma unroll
        for (int ks = 0; ks < 16; ks++) {
            const uint32_t ko = ks * 32;
            uint32_t aqh[4], aql[4];
            LDSM4(aqh, qbh + ko);
            LDSM4(aql, qbl + ko);
#pragma unroll
            for (int jp = 0; jp < 4; jp++) {
                uint32_t bh[4], bl[4];
                LDSM4(bh, kbh[jp] + ko);
                LDSM4(bl, kbl[jp] + ko);
                uint32_t b0h[2] = {bh[0], bh[2]};
                uint32_t b1h[2] = {bh[1], bh[3]};
                uint32_t b0l[2] = {bl[0], bl[2]};
                uint32_t b1l[2] = {bl[1], bl[3]};
                MMA_TF32(s[2 * jp], aqh, b0h);
                MMA_TF32(s[2 * jp], aqh, b0l);
                MMA_TF32(s[2 * jp], aql, b0h);
                MMA_TF32(s[2 * jp + 1], aqh, b1h);
                MMA_TF32(s[2 * jp + 1], aqh, b1l);
                MMA_TF32(s[2 * jp + 1], aql, b1h);
            }
        }

        // ---- causal mask on diagonal tile ----
        if (kt == nkt - 1) {
            const int r0l = w * 16 + g;     // local q row for c0,c1
#pragma unroll
            for (int j = 0; j < 8; j++) {
                int c0 = j * 8 + 2 * tg, c1 = c0 + 1;
                if (c0 > r0l) s[j][0] = -1e9f;
                if (c1 > r0l) s[j][1] = -1e9f;
                if (c0 > r0l + 8) s[j][2] = -1e9f;
                if (c1 > r0l + 8) s[j][3] = -1e9f;
            }
        }

        // ---- online softmax (rows g and g+8; reduce over quad lanes) ----
#pragma unroll
        for (int rr = 0; rr < 2; rr++) {
            float tmax = -1e30f;
#pragma unroll
            for (int j = 0; j < 8; j++) {
                tmax = fmaxf(tmax, fmaxf(s[j][rr * 2], s[j][rr * 2 + 1]));
            }
            tmax = fmaxf(tmax, __shfl_xor_sync(0xffffffffu, tmax, 1));
            tmax = fmaxf(tmax, __shfl_xor_sync(0xffffffffu, tmax, 2));
            float mnew = fmaxf(mrow[rr], tmax);
            float scalef = __expf(mrow[rr] - mnew);
            mrow[rr] = mnew;
            float tsum = 0.f;
#pragma unroll
            for (int j = 0; j < 8; j++) {
                float p0 = __expf(s[j][rr * 2] - mnew);
                float p1 = __expf(s[j][rr * 2 + 1] - mnew);
                s[j][rr * 2] = p0;
                s[j][rr * 2 + 1] = p1;
                tsum += p0 + p1;
            }
            tsum += __shfl_xor_sync(0xffffffffu, tsum, 1);
            tsum += __shfl_xor_sync(0xffffffffu, tsum, 2);
            lrow[rr] = lrow[rr] * scalef + tsum;
#pragma unroll
            for (int dt = 0; dt < 16; dt++) {
                o[dt][rr * 2] *= scalef;
                o[dt][rr * 2 + 1] *= scalef;
            }
        }

        // ---- PV: convert each S tile to A-fragment layout via shfl, mma ----
#pragma unroll
        for (int ks = 0; ks < 8; ks++) {
            const int srcl0 = (g << 2) + (tg >> 1);
            const int srcl1 = srcl0 + 2;
            float v00 = __shfl_sync(0xffffffffu, s[ks][0], srcl0);
            float v01 = __shfl_sync(0xffffffffu, s[ks][1], srcl0);
            float v20 = __shfl_sync(0xffffffffu, s[ks][2], srcl0);
            float v21 = __shfl_sync(0xffffffffu, s[ks][3], srcl0);
            float v40 = __shfl_sync(0xffffffffu, s[ks][0], srcl1);
            float v41 = __shfl_sync(0xffffffffu, s[ks][1], srcl1);
            float v60 = __shfl_sync(0xffffffffu, s[ks][2], srcl1);
            float v61 = __shfl_sync(0xffffffffu, s[ks][3], srcl1);
            bool odd = (tg & 1);
            float a0 = odd ? v01 : v00;
            float a1 = odd ? v21 : v20;
            float a2 = odd ? v41 : v40;
            float a3 = odd ? v61 : v60;
            // 2-term split of P
            float a0h = tf32_rna(a0), a0l = tf32_rna(a0 - a0h);
            float a1h = tf32_rna(a1), a1l = tf32_rna(a1 - a1h);
            float a2h = tf32_rna(a2), a2l = tf32_rna(a2 - a2h);
            float a3h = tf32_rna(a3), a3l = tf32_rna(a3 - a3h);
            uint32_t ah[4] = {__float_as_uint(a0h), __float_as_uint(a1h),
                              __float_as_uint(a2h), __float_as_uint(a3h)};
            uint32_t al[4] = {__float_as_uint(a0l), __float_as_uint(a1l),
                              __float_as_uint(a2l), __float_as_uint(a3l)};
            const int key0 = ks * 8 + tg;
#pragma unroll
            for (int dt = 0; dt < 16; dt++) {
                const int dcol = dt * 8 + g;
                uint32_t bvh[2], bvl[2];
                bvh[0] = __float_as_uint(Vh[key0 * AP + dcol]);
                bvh[1] = __float_as_uint(Vh[(key0 + 4) * AP + dcol]);
                bvl[0] = __float_as_uint(Vl[key0 * AP + dcol]);
                bvl[1] = __float_as_uint(Vl[(key0 + 4) * AP + dcol]);
                MMA_TF32(o[dt], ah, bvh);
                MMA_TF32(o[dt], ah, bvl);
                MMA_TF32(o[dt], al, bvh);
            }
        }
    }

    // ---- epilogue: normalize and store ----
#pragma unroll
    for (int rr = 0; rr < 2; rr++) {
        float invl = 1.0f / lrow[rr];
        int row = q0 + w * 16 + g + rr * 8;
#pragma unroll
        for (int dt = 0; dt < 16; dt++) {
            float2 v;
            v.x = o[dt][rr * 2] * invl;
            v.y = o[dt][rr * 2 + 1] * invl;
            *(float2*)(g_attn + (size_t)row * (NH * HD) + h * HD + dt * 8 + 2 * tg) = v;
        }
    }
}

// ---------------- launch -----------------------------------------------------
extern "C" void kernel_launch(void* const* d_in, const int* in_sizes, int n_in,
                              void* d_out, int out_size) {
    const float* hidden = (const float*)d_in[0];
    const float* cosb   = (const float*)d_in[1];
    const float* sinb   = (const float*)d_in[2];
    const float* kcache = (const float*)d_in[3];
    const float* vcache = (const float*)d_in[4];
    const float* wqkv   = (const float*)d_in[6];
    const float* bqkv   = (const float*)d_in[7];
    const float* wo     = (const float*)d_in[8];
    const float* bo     = (const float*)d_in[9];
    const float* qw     = (const float*)d_in[10];
    const float* kw     = (const float*)d_in[11];
    const int*   widx   = (const int*)d_in[12];
    float* out = (float*)d_out;

    float *p_qkv, *p_attn;
    cudaGetSymbolAddress((void**)&p_qkv, g_qkv);
    cudaGetSymbolAddress((void**)&p_attn, g_attn);

    static bool attr_set = false;
    if (!attr_set) {
        cudaFuncSetAttribute(gemm_tc, cudaFuncAttributeMaxDynamicSharedMemorySize, G_SMEM_BYTES);
        cudaFuncSetAttribute(attn_tc, cudaFuncAttributeMaxDynamicSharedMemorySize, ATTN_SMEM2);
        attr_set = true;
    }

    // 1. QKV GEMM: [2048,3072] = hidden @ wqkv^T + bqkv  (3xTF32 mma + ldsm)
    gemm_tc<<<dim3(QKV_OUT / 128, S_LEN / 128), 256, G_SMEM_BYTES>>>(
        hidden, wqkv, bqkv, p_qkv, QKV_OUT, HID);

    // 2. caches -> scratch
    copy_caches<<<256, 256>>>(kcache, vcache);

    // 3. RMSNorm + RoPE + scale + scatter
    norm_rope_scatter<<<dim3(S_LEN, 24), 128>>>(cosb, sinb, qw, kw, widx);

    // 4. tensor-core flash attention
    attn_tc<<<dim3(S_LEN / 64, NH), 128, ATTN_SMEM2>>>();

    // 5. output projection: [2048,2048] = attn @ wo^T + bo
    gemm_tc<<<dim3(HID / 128, S_LEN / 128), 256, G_SMEM_BYTES>>>(
        p_attn, wo, bo, out, HID, NH * HD);
}

// round 6
// speedup vs baseline: 3.1135x; 1.8883x over previous
#include <cuda_runtime.h>
#include <cuda_bf16.h>
#include <cstdint>
#include <math.h>

// Problem constants
#define S_LEN 2048
#define HID 2048
#define NH 16
#define NKV 4
#define HD 128
#define QKV_OUT 3072
#define Q_SZ 2048
#define KV_SZ 512
#define SCALE_Q 0.08838834764831845f

typedef __nv_bfloat16 bf16;

// ---------------- scratch ----------------------------------------------------
__device__ float g_qkv[S_LEN * QKV_OUT];
__device__ bf16 g_hidh[S_LEN * HID], g_hidl[S_LEN * HID];
__device__ bf16 g_wqh[QKV_OUT * HID], g_wql[QKV_OUT * HID];
__device__ bf16 g_woh[HID * HID], g_wol[HID * HID];
__device__ bf16 g_qh[S_LEN * NH * HD], g_ql[S_LEN * NH * HD];
__device__ bf16 g_kh[S_LEN * NKV * HD], g_kl[S_LEN * NKV * HD];
__device__ bf16 g_vh[S_LEN * NKV * HD], g_vl[S_LEN * NKV * HD];
__device__ bf16 g_ah[S_LEN * NH * HD], g_al[S_LEN * NH * HD];

// ---------------- helpers ----------------------------------------------------
__device__ __forceinline__ uint32_t smem_u32(const void* p) {
    return (uint32_t)__cvta_generic_to_shared(p);
}
__device__ __forceinline__ float bfhi(float x) {
    return __bfloat162float(__float2bfloat16(x));
}
// pack two floats into bf16x2 (lo_v -> low half)
__device__ __forceinline__ uint32_t packbf(float lo_v, float hi_v) {
    uint32_t r;
    asm("cvt.rn.bf16x2.f32 %0, %1, %2;" : "=r"(r) : "f"(hi_v), "f"(lo_v));
    return r;
}

#define MMA_BF(d, a, b) \
    asm volatile( \
        "mma.sync.aligned.m16n8k16.row.col.f32.bf16.bf16.f32 " \
        "{%0,%1,%2,%3}, {%4,%5,%6,%7}, {%8,%9}, {%0,%1,%2,%3};" \
        : "+f"((d)[0]), "+f"((d)[1]), "+f"((d)[2]), "+f"((d)[3]) \
        : "r"((a)[0]), "r"((a)[1]), "r"((a)[2]), "r"((a)[3]), \
          "r"((b)[0]), "r"((b)[1]))

#define LDSM4(r, addr) \
    asm volatile("ldmatrix.sync.aligned.m8n8.x4.shared.b16 {%0,%1,%2,%3}, [%4];" \
        : "=r"((r)[0]), "=r"((r)[1]), "=r"((r)[2]), "=r"((r)[3]) : "r"(addr))

#define LDSM4T(r, addr) \
    asm volatile("ldmatrix.sync.aligned.m8n8.x4.trans.shared.b16 {%0,%1,%2,%3}, [%4];" \
        : "=r"((r)[0]), "=r"((r)[1]), "=r"((r)[2]), "=r"((r)[3]) : "r"(addr))

// ---------------- split kernels ---------------------------------------------
__global__ void split_bf16k(const float* __restrict__ src, bf16* __restrict__ hi,
                            bf16* __restrict__ lo, int n4) {
    __nv_bfloat162* H = (__nv_bfloat162*)hi;
    __nv_bfloat162* L = (__nv_bfloat162*)lo;
    for (int i = blockIdx.x * blockDim.x + threadIdx.x; i < n4;
         i += gridDim.x * blockDim.x) {
        float4 v = ((const float4*)src)[i];
        bf16 h0 = __float2bfloat16(v.x), h1 = __float2bfloat16(v.y);
        bf16 h2 = __float2bfloat16(v.z), h3 = __float2bfloat16(v.w);
        bf16 l0 = __float2bfloat16(v.x - __bfloat162float(h0));
        bf16 l1 = __float2bfloat16(v.y - __bfloat162float(h1));
        bf16 l2 = __float2bfloat16(v.z - __bfloat162float(h2));
        bf16 l3 = __float2bfloat16(v.w - __bfloat162float(h3));
        H[2 * i] = __nv_bfloat162(h0, h1);
        H[2 * i + 1] = __nv_bfloat162(h2, h3);
        L[2 * i] = __nv_bfloat162(l0, l1);
        L[2 * i + 1] = __nv_bfloat162(l2, l3);
    }
}

__global__ void copy_caches(const float* __restrict__ kc, const float* __restrict__ vc) {
    int n = S_LEN * NKV * HD;
    for (int i = blockIdx.x * blockDim.x + threadIdx.x; i < n;
         i += gridDim.x * blockDim.x) {
        float k = kc[i], v = vc[i];
        bf16 kh = __float2bfloat16(k);
        bf16 vh = __float2bfloat16(v);
        g_kh[i] = kh; g_kl[i] = __float2bfloat16(k - __bfloat162float(kh));
        g_vh[i] = vh; g_vl[i] = __float2bfloat16(v - __bfloat162float(vh));
    }
}

// ---------------- fused RMSNorm + RoPE + scale + scatter (bf16 hi/lo out) ----
__global__ void norm_rope_scatter(const float* __restrict__ cosb,
                                  const float* __restrict__ sinb,
                                  const float* __restrict__ qw,
                                  const float* __restrict__ kw,
                                  const int* __restrict__ widx) {
    const int s = blockIdx.x;
    const int head = blockIdx.y;
    const int d = threadIdx.x;
    __shared__ float sh[128];
    __shared__ float wsum[4];

    int col;
    if (head < 16)      col = head * HD + d;
    else if (head < 20) col = Q_SZ + (head - 16) * HD + d;
    else                col = Q_SZ + KV_SZ + (head - 20) * HD + d;

    float x = g_qkv[(size_t)s * QKV_OUT + col];

    if (head >= 20) {
        size_t o = ((size_t)widx[s] * NKV + (head - 20)) * HD + d;
        bf16 h = __float2bfloat16(x);
        g_vh[o] = h;
        g_vl[o] = __float2bfloat16(x - __bfloat162float(h));
        return;
    }

    float sq = x * x;
#pragma unroll
    for (int m = 16; m; m >>= 1) sq += __shfl_xor_sync(0xffffffffu, sq, m);
    if ((d & 31) == 0) wsum[d >> 5] = sq;
    __syncthreads();
    float ms = (wsum[0] + wsum[1] + wsum[2] + wsum[3]) * (1.0f / 128.0f);
    float inv = rsqrtf(ms + 1e-6f);
    const float* w = (head < 16) ? qw : kw;
    float y = x * inv * w[d];
    sh[d] = y;
    __syncthreads();

    if (d < 64) {
        float c = cosb[s * 64 + d], sn = sinb[s * 64 + d];
        float x1 = sh[d], x2 = sh[d + 64];
        float y1 = x1 * c - x2 * sn;
        float y2 = x1 * sn + x2 * c;
        if (head < 16) {
            y1 *= SCALE_Q; y2 *= SCALE_Q;
            size_t o = ((size_t)s * NH + head) * HD;
            bf16 h1 = __float2bfloat16(y1), h2 = __float2bfloat16(y2);
            g_qh[o + d] = h1;
            g_ql[o + d] = __float2bfloat16(y1 - __bfloat162float(h1));
            g_qh[o + d + 64] = h2;
            g_ql[o + d + 64] = __float2bfloat16(y2 - __bfloat162float(h2));
        } else {
            size_t o = ((size_t)widx[s] * NKV + (head - 16)) * HD;
            bf16 h1 = __float2bfloat16(y1), h2 = __float2bfloat16(y2);
            g_kh[o + d] = h1;
            g_kl[o + d] = __float2bfloat16(y1 - __bfloat162float(h1));
            g_kh[o + d + 64] = h2;
            g_kl[o + d + 64] = __float2bfloat16(y2 - __bfloat162float(h2));
        }
    }
}

// =================== 3xBF16 mma.sync GEMM ====================================
// C[M,N] = (Ah+Al)[M,K] @ (Bh+Bl)[N,K]^T + bias[N].
// CTA 128x128, 256 thr (8 warps 4x2, warp 32x64), k-chunk 32, double-buffered.
#define GSTRIDE 40                        // bf16 elems per smem row
#define GBUF_E (128 * GSTRIDE)            // 5120 elems
#define GBUF_B (GBUF_E * 2)               // 10240 bytes
#define GSTAGE_E (4 * GBUF_E)             // 20480 elems
#define GSTAGE_B (GSTAGE_E * 2)           // 40960 bytes
#define G_SMEM (2 * GSTAGE_B)             // 81920 bytes

__global__ void __launch_bounds__(256)
gemm_bf(const bf16* __restrict__ Ah_g, const bf16* __restrict__ Al_g,
        const bf16* __restrict__ Bh_g, const bf16* __restrict__ Bl_g,
        const float* __restrict__ bias, float* __restrict__ C,
        int N, int K) {
    extern __shared__ bf16 smg[];
    const int t = threadIdx.x;
    const int lane = t & 31, wid = t >> 5;
    const int g = lane >> 2, tg = lane & 3;
    const int wm = (wid & 3) * 32, wn = (wid >> 2) * 64;
    const int m0 = blockIdx.y << 7, n0 = blockIdx.x << 7;
    const int nch = K >> 5;

    const int l15 = lane & 15, lh = lane >> 4;
    const uint32_t sb = smem_u32(smg);
    const uint32_t offA = (uint32_t)((wm + l15) * 80 + lh * 16);
    const uint32_t offB = (uint32_t)((wn + l15) * 80 + lh * 16);

    float d[2][8][4];
#pragma unroll
    for (int i = 0; i < 2; i++)
#pragma unroll
        for (int j = 0; j < 8; j++)
#pragma unroll
            for (int q = 0; q < 4; q++) d[i][j][q] = 0.f;

    uint4 st[8];

#define G_LOADC(c) do { \
    _Pragma("unroll") \
    for (int j = 0; j < 2; j++) { \
        int u = t + (j << 8); int row = u >> 2, c8 = u & 3; \
        size_t ao = (size_t)(m0 + row) * K + ((c) << 5) + (c8 << 3); \
        size_t bo = (size_t)(n0 + row) * K + ((c) << 5) + (c8 << 3); \
        st[j]     = *(const uint4*)(Ah_g + ao); \
        st[2 + j] = *(const uint4*)(Al_g + ao); \
        st[4 + j] = *(const uint4*)(Bh_g + bo); \
        st[6 + j] = *(const uint4*)(Bl_g + bo); \
    } } while (0)

#define G_STSC(stg) do { \
    bf16* base = smg + (stg) * GSTAGE_E; \
    _Pragma("unroll") \
    for (int j = 0; j < 2; j++) { \
        int u = t + (j << 8); int row = u >> 2, c8 = u & 3; \
        int dst = row * GSTRIDE + (c8 << 3); \
        *(uint4*)(base + dst) = st[j]; \
        *(uint4*)(base + GBUF_E + dst) = st[2 + j]; \
        *(uint4*)(base + 2 * GBUF_E + dst) = st[4 + j]; \
        *(uint4*)(base + 3 * GBUF_E + dst) = st[6 + j]; \
    } } while (0)

    G_LOADC(0);
    G_STSC(0);
    __syncthreads();

    for (int c = 0; c < nch; c++) {
        const int stg = c & 1;
        if (c + 1 < nch) G_LOADC(c + 1);

        const uint32_t base = sb + stg * GSTAGE_B;
#pragma unroll
        for (int ks = 0; ks < 2; ks++) {
            const uint32_t ko = ks * 32;
            uint32_t ah[2][4], al[2][4];
#pragma unroll
            for (int mt = 0; mt < 2; mt++) {
                LDSM4(ah[mt], base + offA + mt * 1280 + ko);
                LDSM4(al[mt], base + GBUF_B + offA + mt * 1280 + ko);
            }
#pragma unroll
            for (int jp = 0; jp < 4; jp++) {
                uint32_t bh4[4], bl4[4];
                LDSM4(bh4, base + 2 * GBUF_B + offB + jp * 1280 + ko);
                LDSM4(bl4, base + 3 * GBUF_B + offB + jp * 1280 + ko);
                uint32_t b0h[2] = {bh4[0], bh4[2]}, b1h[2] = {bh4[1], bh4[3]};
                uint32_t b0l[2] = {bl4[0], bl4[2]}, b1l[2] = {bl4[1], bl4[3]};
#pragma unroll
                for (int mt = 0; mt < 2; mt++) {
                    MMA_BF(d[mt][2 * jp], ah[mt], b0h);
                    MMA_BF(d[mt][2 * jp], ah[mt], b0l);
                    MMA_BF(d[mt][2 * jp], al[mt], b0h);
                    MMA_BF(d[mt][2 * jp + 1], ah[mt], b1h);
                    MMA_BF(d[mt][2 * jp + 1], ah[mt], b1l);
                    MMA_BF(d[mt][2 * jp + 1], al[mt], b1h);
                }
            }
        }

        if (c + 1 < nch) {
            __syncthreads();
            G_STSC(stg ^ 1);
            __syncthreads();
        }
    }

    // epilogue
#pragma unroll
    for (int i = 0; i < 2; i++) {
        int r = m0 + wm + i * 16 + g;
#pragma unroll
        for (int j = 0; j < 8; j++) {
            int cix = n0 + wn + j * 8 + tg * 2;
            float2 b2 = *(const float2*)(bias + cix);
            float2 v0, v1;
            v0.x = d[i][j][0] + b2.x; v0.y = d[i][j][1] + b2.y;
            v1.x = d[i][j][2] + b2.x; v1.y = d[i][j][3] + b2.y;
            *(float2*)(C + (size_t)r * N + cix) = v0;
            *(float2*)(C + (size_t)(r + 8) * N + cix) = v1;
        }
    }
#undef G_LOADC
#undef G_STSC
}

// =================== bf16 tensor-core flash attention ========================
// 256 threads (8 warps), CTA = 128 q rows of one head; warp w owns rows
// [16w,16w+16). k-tiles of 64 keys. 3xBF16 scores and PV.
#define APAD 136                       // bf16 elems per smem row (272 B)
#define QBUF_E (128 * APAD)            // 17408 elems
#define KVBUF_E (64 * APAD)            // 8704 elems
#define ATTN_SMEM ((2 * QBUF_E + 4 * KVBUF_E) * 2)   // 139264 bytes

__global__ void __launch_bounds__(256, 1) attn_tc() {
    extern __shared__ bf16 sma[];
    bf16* Qh = sma;
    bf16* Ql = sma + QBUF_E;
    bf16* Kh = sma + 2 * QBUF_E;
    bf16* Kl = Kh + KVBUF_E;
    bf16* Vh = Kh + 2 * KVBUF_E;
    bf16* Vl = Kh + 3 * KVBUF_E;

    const int t = threadIdx.x;
    const int lane = t & 31, w = t >> 5;
    const int g = lane >> 2, tg = lane & 3;
    const int qt = gridDim.x - 1 - blockIdx.x;    // heavy CTAs first
    const int q0 = qt * 128;
    const int h = blockIdx.y, kvh = h >> 2;
    const int wq = w * 16;

    // ---- stage Q (bf16 hi/lo) ----
#pragma unroll
    for (int i = 0; i < 8; i++) {
        int u = t + i * 256;                 // 0..2047
        int r = u >> 4, cc = u & 15;
        size_t qo = ((size_t)(q0 + r) * NH + h) * HD + cc * 8;
        *(uint4*)((char*)Qh + r * 272 + cc * 16) = *(const uint4*)(g_qh + qo);
        *(uint4*)((char*)Ql + r * 272 + cc * 16) = *(const uint4*)(g_ql + qo);
    }

    const int l15 = lane & 15, lh = lane >> 4;
    const uint32_t qb_h = smem_u32(Qh) + (wq + l15) * 272 + lh * 16;
    const uint32_t qb_l = qb_h + QBUF_E * 2;
    uint32_t kb_h[4];
#pragma unroll
    for (int jp = 0; jp < 4; jp++)
        kb_h[jp] = smem_u32(Kh) + (jp * 16 + l15) * 272 + lh * 16;
    const uint32_t vb_h = smem_u32(Vh) + l15 * 272 + lh * 16;

    float o[16][4];
#pragma unroll
    for (int dt = 0; dt < 16; dt++)
#pragma unroll
        for (int q = 0; q < 4; q++) o[dt][q] = 0.f;
    float mrow[2] = {-1e30f, -1e30f};
    float lrow[2] = {0.f, 0.f};

    const int nkt = 2 * (qt + 1);
    for (int kt = 0; kt < nkt; kt++) {
        const int k0 = kt * 64;
        __syncthreads();
        // ---- stage K, V tiles ----
#pragma unroll
        for (int i = 0; i < 4; i++) {
            int u = t + i * 256;             // 0..1023
            int r = u >> 4, cc = u & 15;
            size_t so = ((size_t)(k0 + r) * NKV + kvh) * HD + cc * 8;
            int dd = r * 272 + cc * 16;
            *(uint4*)((char*)Kh + dd) = *(const uint4*)(g_kh + so);
            *(uint4*)((char*)Kl + dd) = *(const uint4*)(g_kl + so);
            *(uint4*)((char*)Vh + dd) = *(const uint4*)(g_vh + so);
            *(uint4*)((char*)Vl + dd) = *(const uint4*)(g_vl + so);
        }
        __syncthreads();

        // ---- scores S[16q x 64k] (3xBF16 over d=128) ----
        float s[8][4];
#pragma unroll
        for (int j = 0; j < 8; j++)
#pragma unroll
            for (int q = 0; q < 4; q++) s[j][q] = 0.f;

#pragma unroll
        for (int ks = 0; ks < 8; ks++) {
            const uint32_t ko = ks * 32;
            uint32_t aqh[4], aql[4];
            LDSM4(aqh, qb_h + ko);
            LDSM4(aql, qb_l + ko);
#pragma unroll
            for (int jp = 0; jp < 4; jp++) {
                uint32_t kh4[4], kl4[4];
                LDSM4(kh4, kb_h[jp] + ko);
                LDSM4(kl4, kb_h[jp] + KVBUF_E * 2 + ko);
                uint32_t b0h[2] = {kh4[0], kh4[2]}, b1h[2] = {kh4[1], kh4[3]};
                uint32_t b0l[2] = {kl4[0], kl4[2]}, b1l[2] = {kl4[1], kl4[3]};
                MMA_BF(s[2 * jp], aqh, b0h);
                MMA_BF(s[2 * jp], aqh, b0l);
                MMA_BF(s[2 * jp], aql, b0h);
                MMA_BF(s[2 * jp + 1], aqh, b1h);
                MMA_BF(s[2 * jp + 1], aqh, b1l);
                MMA_BF(s[2 * jp + 1], aql, b1h);
            }
        }

        // ---- causal mask (last two tiles only) ----
        if (kt >= nkt - 2) {
            const int rbase = q0 + wq + g;
#pragma unroll
            for (int j = 0; j < 8; j++) {
                int cg = k0 + 8 * j + 2 * tg;
                if (cg > rbase) s[j][0] = -1e9f;
                if (cg + 1 > rbase) s[j][1] = -1e9f;
                if (cg > rbase + 8) s[j][2] = -1e9f;
                if (cg + 1 > rbase + 8) s[j][3] = -1e9f;
            }
        }

        // ---- online softmax ----
#pragma unroll
        for (int rr = 0; rr < 2; rr++) {
            float tmax = -1e30f;
#pragma unroll
            for (int j = 0; j < 8; j++)
                tmax = fmaxf(tmax, fmaxf(s[j][rr * 2], s[j][rr * 2 + 1]));
            tmax = fmaxf(tmax, __shfl_xor_sync(0xffffffffu, tmax, 1));
            tmax = fmaxf(tmax, __shfl_xor_sync(0xffffffffu, tmax, 2));
            float mnew = fmaxf(mrow[rr], tmax);
            float scalef = __expf(mrow[rr] - mnew);
            mrow[rr] = mnew;
            float tsum = 0.f;
#pragma unroll
            for (int j = 0; j < 8; j++) {
                float p0 = __expf(s[j][rr * 2] - mnew);
                float p1 = __expf(s[j][rr * 2 + 1] - mnew);
                s[j][rr * 2] = p0;
                s[j][rr * 2 + 1] = p1;
                tsum += p0 + p1;
            }
            tsum += __shfl_xor_sync(0xffffffffu, tsum, 1);
            tsum += __shfl_xor_sync(0xffffffffu, tsum, 2);
            lrow[rr] = lrow[rr] * scalef + tsum;
#pragma unroll
            for (int dt = 0; dt < 16; dt++) {
                o[dt][rr * 2] *= scalef;
                o[dt][rr * 2 + 1] *= scalef;
            }
        }

        // ---- PV: P fragments from accumulator regs; V via ldmatrix.trans ----
#pragma unroll
        for (int c = 0; c < 4; c++) {     // k16 chunks of 64 keys
            uint32_t pah[4], pal[4];
#pragma unroll
            for (int hq = 0; hq < 2; hq++) {          // s[2c], s[2c+1]
                float p0 = s[2 * c + hq][0], p1 = s[2 * c + hq][1];
                float p2 = s[2 * c + hq][2], p3 = s[2 * c + hq][3];
                float h0 = bfhi(p0), h1 = bfhi(p1), h2 = bfhi(p2), h3 = bfhi(p3);
                pah[hq * 2 + 0] = packbf(p0, p1);      // rows g
                pah[hq * 2 + 1] = packbf(p2, p3);      // rows g+8
                pal[hq * 2 + 0] = packbf(p0 - h0, p1 - h1);
                pal[hq * 2 + 1] = packbf(p2 - h2, p3 - h3);
            }
            // a0 = rows g k0-7 -> pack(s[2c][0..1]); a1 = rows g+8; a2/a3 k8-15
            uint32_t A_h[4] = {pah[0], pah[1], pah[2], pah[3]};
            uint32_t A_l[4] = {pal[0], pal[1], pal[2], pal[3]};
            const uint32_t vrow = vb_h + c * (16 * 272);
#pragma unroll
            for (int dt16 = 0; dt16 < 8; dt16++) {
                uint32_t vh4[4], vl4[4];
                LDSM4T(vh4, vrow + dt16 * 32);
                LDSM4T(vl4, vrow + KVBUF_E * 2 + dt16 * 32);
                uint32_t bv0h[2] = {vh4[0], vh4[1]}, bv1h[2] = {vh4[2], vh4[3]};
                uint32_t bv0l[2] = {vl4[0], vl4[1]}, bv1l[2] = {vl4[2], vl4[3]};
                MMA_BF(o[2 * dt16], A_h, bv0h);
                MMA_BF(o[2 * dt16], A_h, bv0l);
                MMA_BF(o[2 * dt16], A_l, bv0h);
                MMA_BF(o[2 * dt16 + 1], A_h, bv1h);
                MMA_BF(o[2 * dt16 + 1], A_h, bv1l);
                MMA_BF(o[2 * dt16 + 1], A_l, bv1h);
            }
        }
    }

    // ---- epilogue: normalize, split to bf16 hi/lo, store ----
#pragma unroll
    for (int rr = 0; rr < 2; rr++) {
        float invl = 1.0f / lrow[rr];
        int row = q0 + wq + g + rr * 8;
#pragma unroll
        for (int dt = 0; dt < 16; dt++) {
            float x0 = o[dt][rr * 2] * invl;
            float x1 = o[dt][rr * 2 + 1] * invl;
            float h0 = bfhi(x0), h1 = bfhi(x1);
            size_t off = (size_t)row * (NH * HD) + h * HD + dt * 8 + 2 * tg;
            *(uint32_t*)(g_ah + off) = packbf(x0, x1);
            *(uint32_t*)(g_al + off) = packbf(x0 - h0, x1 - h1);
        }
    }
}

// ---------------- launch -----------------------------------------------------
extern "C" void kernel_launch(void* const* d_in, const int* in_sizes, int n_in,
                              void* d_out, int out_size) {
    const float* hidden = (const float*)d_in[0];
    const float* cosb   = (const float*)d_in[1];
    const float* sinb   = (const float*)d_in[2];
    const float* kcache = (const float*)d_in[3];
    const float* vcache = (const float*)d_in[4];
    const float* wqkv   = (const float*)d_in[6];
    const float* bqkv   = (const float*)d_in[7];
    const float* wo     = (const float*)d_in[8];
    const float* bo     = (const float*)d_in[9];
    const float* qw     = (const float*)d_in[10];
    const float* kw     = (const float*)d_in[11];
    const int*   widx   = (const int*)d_in[12];
    float* out = (float*)d_out;

    float* p_qkv;
    bf16 *p_hidh, *p_hidl, *p_wqh, *p_wql, *p_woh, *p_wol, *p_ah, *p_al;
    cudaGetSymbolAddress((void**)&p_qkv, g_qkv);
    cudaGetSymbolAddress((void**)&p_hidh, g_hidh);
    cudaGetSymbolAddress((void**)&p_hidl, g_hidl);
    cudaGetSymbolAddress((void**)&p_wqh, g_wqh);
    cudaGetSymbolAddress((void**)&p_wql, g_wql);
    cudaGetSymbolAddress((void**)&p_woh, g_woh);
    cudaGetSymbolAddress((void**)&p_wol, g_wol);
    cudaGetSymbolAddress((void**)&p_ah, g_ah);
    cudaGetSymbolAddress((void**)&p_al, g_al);

    static bool attr_set = false;
    if (!attr_set) {
        cudaFuncSetAttribute(gemm_bf, cudaFuncAttributeMaxDynamicSharedMemorySize, G_SMEM);
        cudaFuncSetAttribute(attn_tc, cudaFuncAttributeMaxDynamicSharedMemorySize, ATTN_SMEM);
        attr_set = true;
    }

    // 0. split inputs to bf16 hi/lo
    split_bf16k<<<1024, 256>>>(hidden, p_hidh, p_hidl, S_LEN * HID / 4);
    split_bf16k<<<1024, 256>>>(wqkv, p_wqh, p_wql, QKV_OUT * HID / 4);
    split_bf16k<<<1024, 256>>>(wo, p_woh, p_wol, HID * HID / 4);

    // 1. QKV GEMM (3xBF16): [2048,3072]
    gemm_bf<<<dim3(QKV_OUT / 128, S_LEN / 128), 256, G_SMEM>>>(
        p_hidh, p_hidl, p_wqh, p_wql, bqkv, p_qkv, QKV_OUT, HID);

    // 2. caches -> split scratch
    copy_caches<<<256, 256>>>(kcache, vcache);

    // 3. RMSNorm + RoPE + scale + scatter (writes bf16 hi/lo q/k/v)
    norm_rope_scatter<<<dim3(S_LEN, 24), 128>>>(cosb, sinb, qw, kw, widx);

    // 4. bf16 tensor-core flash attention (writes bf16 hi/lo attn out)
    attn_tc<<<dim3(S_LEN / 128, NH), 256, ATTN_SMEM>>>();

    // 5. output projection (3xBF16): [2048,2048]
    gemm_bf<<<dim3(HID / 128, S_LEN / 128), 256, G_SMEM>>>(
        p_ah, p_al, p_woh, p_wol, bo, out, HID, NH * HD);
}

// round 7
// speedup vs baseline: 3.2151x; 1.0326x over previous
#include <cuda_runtime.h>
#include <cuda_bf16.h>
#include <cstdint>
#include <math.h>

// Problem constants
#define S_LEN 2048
#define HID 2048
#define NH 16
#define NKV 4
#define HD 128
#define QKV_OUT 3072
#define Q_SZ 2048
#define KV_SZ 512
#define SCALE_Q 0.08838834764831845f

typedef __nv_bfloat16 bf16;

// ---------------- scratch ----------------------------------------------------
__device__ float g_qkv[S_LEN * QKV_OUT];
__device__ bf16 g_hidh[S_LEN * HID], g_hidl[S_LEN * HID];
__device__ bf16 g_wqh[QKV_OUT * HID], g_wql[QKV_OUT * HID];
__device__ bf16 g_woh[HID * HID], g_wol[HID * HID];
__device__ bf16 g_qh[S_LEN * NH * HD], g_ql[S_LEN * NH * HD];
__device__ bf16 g_kh[S_LEN * NKV * HD], g_kl[S_LEN * NKV * HD];
__device__ bf16 g_vh[S_LEN * NKV * HD], g_vl[S_LEN * NKV * HD];
__device__ bf16 g_ah[S_LEN * NH * HD], g_al[S_LEN * NH * HD];

// ---------------- helpers ----------------------------------------------------
__device__ __forceinline__ uint32_t smem_u32(const void* p) {
    return (uint32_t)__cvta_generic_to_shared(p);
}
__device__ __forceinline__ float bfhi(float x) {
    return __bfloat162float(__float2bfloat16(x));
}
__device__ __forceinline__ uint32_t packbf(float lo_v, float hi_v) {
    uint32_t r;
    asm("cvt.rn.bf16x2.f32 %0, %1, %2;" : "=r"(r) : "f"(hi_v), "f"(lo_v));
    return r;
}

#define MMA_BF(d, a, b) \
    asm volatile( \
        "mma.sync.aligned.m16n8k16.row.col.f32.bf16.bf16.f32 " \
        "{%0,%1,%2,%3}, {%4,%5,%6,%7}, {%8,%9}, {%0,%1,%2,%3};" \
        : "+f"((d)[0]), "+f"((d)[1]), "+f"((d)[2]), "+f"((d)[3]) \
        : "r"((a)[0]), "r"((a)[1]), "r"((a)[2]), "r"((a)[3]), \
          "r"((b)[0]), "r"((b)[1]))

#define LDSM4(r, addr) \
    asm volatile("ldmatrix.sync.aligned.m8n8.x4.shared.b16 {%0,%1,%2,%3}, [%4];" \
        : "=r"((r)[0]), "=r"((r)[1]), "=r"((r)[2]), "=r"((r)[3]) : "r"(addr))

#define LDSM4T(r, addr) \
    asm volatile("ldmatrix.sync.aligned.m8n8.x4.trans.shared.b16 {%0,%1,%2,%3}, [%4];" \
        : "=r"((r)[0]), "=r"((r)[1]), "=r"((r)[2]), "=r"((r)[3]) : "r"(addr))

#define CP16(dst, src) \
    asm volatile("cp.async.cg.shared.global [%0], [%1], 16;" :: "r"(dst), "l"(src))
#define CP_COMMIT() asm volatile("cp.async.commit_group;" ::: "memory")
#define CP_WAIT(n) asm volatile("cp.async.wait_group %0;" :: "n"(n) : "memory")

// ---------------- split kernels ---------------------------------------------
__global__ void split_bf16k(const float* __restrict__ src, bf16* __restrict__ hi,
                            bf16* __restrict__ lo, int n4) {
    __nv_bfloat162* H = (__nv_bfloat162*)hi;
    __nv_bfloat162* L = (__nv_bfloat162*)lo;
    for (int i = blockIdx.x * blockDim.x + threadIdx.x; i < n4;
         i += gridDim.x * blockDim.x) {
        float4 v = ((const float4*)src)[i];
        bf16 h0 = __float2bfloat16(v.x), h1 = __float2bfloat16(v.y);
        bf16 h2 = __float2bfloat16(v.z), h3 = __float2bfloat16(v.w);
        bf16 l0 = __float2bfloat16(v.x - __bfloat162float(h0));
        bf16 l1 = __float2bfloat16(v.y - __bfloat162float(h1));
        bf16 l2 = __float2bfloat16(v.z - __bfloat162float(h2));
        bf16 l3 = __float2bfloat16(v.w - __bfloat162float(h3));
        H[2 * i] = __nv_bfloat162(h0, h1);
        H[2 * i + 1] = __nv_bfloat162(h2, h3);
        L[2 * i] = __nv_bfloat162(l0, l1);
        L[2 * i + 1] = __nv_bfloat162(l2, l3);
    }
}

__global__ void copy_caches(const float* __restrict__ kc, const float* __restrict__ vc) {
    int n = S_LEN * NKV * HD;
    for (int i = blockIdx.x * blockDim.x + threadIdx.x; i < n;
         i += gridDim.x * blockDim.x) {
        float k = kc[i], v = vc[i];
        bf16 kh = __float2bfloat16(k);
        bf16 vh = __float2bfloat16(v);
        g_kh[i] = kh; g_kl[i] = __float2bfloat16(k - __bfloat162float(kh));
        g_vh[i] = vh; g_vl[i] = __float2bfloat16(v - __bfloat162float(vh));
    }
}

// ---------------- fused RMSNorm + RoPE + scale + scatter ---------------------
__global__ void norm_rope_scatter(const float* __restrict__ cosb,
                                  const float* __restrict__ sinb,
                                  const float* __restrict__ qw,
                                  const float* __restrict__ kw,
                                  const int* __restrict__ widx) {
    const int s = blockIdx.x;
    const int head = blockIdx.y;
    const int d = threadIdx.x;
    __shared__ float sh[128];
    __shared__ float wsum[4];

    int col;
    if (head < 16)      col = head * HD + d;
    else if (head < 20) col = Q_SZ + (head - 16) * HD + d;
    else                col = Q_SZ + KV_SZ + (head - 20) * HD + d;

    float x = g_qkv[(size_t)s * QKV_OUT + col];

    if (head >= 20) {
        size_t o = ((size_t)widx[s] * NKV + (head - 20)) * HD + d;
        bf16 h = __float2bfloat16(x);
        g_vh[o] = h;
        g_vl[o] = __float2bfloat16(x - __bfloat162float(h));
        return;
    }

    float sq = x * x;
#pragma unroll
    for (int m = 16; m; m >>= 1) sq += __shfl_xor_sync(0xffffffffu, sq, m);
    if ((d & 31) == 0) wsum[d >> 5] = sq;
    __syncthreads();
    float ms = (wsum[0] + wsum[1] + wsum[2] + wsum[3]) * (1.0f / 128.0f);
    float inv = rsqrtf(ms + 1e-6f);
    const float* w = (head < 16) ? qw : kw;
    float y = x * inv * w[d];
    sh[d] = y;
    __syncthreads();

    if (d < 64) {
        float c = cosb[s * 64 + d], sn = sinb[s * 64 + d];
        float x1 = sh[d], x2 = sh[d + 64];
        float y1 = x1 * c - x2 * sn;
        float y2 = x1 * sn + x2 * c;
        if (head < 16) {
            y1 *= SCALE_Q; y2 *= SCALE_Q;
            size_t o = ((size_t)s * NH + head) * HD;
            bf16 h1 = __float2bfloat16(y1), h2 = __float2bfloat16(y2);
            g_qh[o + d] = h1;
            g_ql[o + d] = __float2bfloat16(y1 - __bfloat162float(h1));
            g_qh[o + d + 64] = h2;
            g_ql[o + d + 64] = __float2bfloat16(y2 - __bfloat162float(h2));
        } else {
            size_t o = ((size_t)widx[s] * NKV + (head - 16)) * HD;
            bf16 h1 = __float2bfloat16(y1), h2 = __float2bfloat16(y2);
            g_kh[o + d] = h1;
            g_kl[o + d] = __float2bfloat16(y1 - __bfloat162float(h1));
            g_kh[o + d + 64] = h2;
            g_kl[o + d + 64] = __float2bfloat16(y2 - __bfloat162float(h2));
        }
    }
}

// =================== 3xBF16 GEMM with cp.async 4-stage pipeline ==============
// C[M,N] = (Ah+Al)[M,K] @ (Bh+Bl)[N,K]^T + bias[N].
// CTA 128x128, 256 thr, warp 32x64, k-chunk 32, 4-stage cp.async ring.
#define GSTRIDE 40                        // bf16 elems per smem row
#define GBUF_E (128 * GSTRIDE)            // 5120 elems
#define GBUF_B (GBUF_E * 2)               // 10240 bytes
#define GSTAGE_B (4 * GBUF_B)             // 40960 bytes
#define G_SMEM (4 * GSTAGE_B)             // 163840 bytes

__global__ void __launch_bounds__(256)
gemm_bf(const bf16* __restrict__ Ah_g, const bf16* __restrict__ Al_g,
        const bf16* __restrict__ Bh_g, const bf16* __restrict__ Bl_g,
        const float* __restrict__ bias, float* __restrict__ C,
        int N, int K) {
    extern __shared__ bf16 smg[];
    const int t = threadIdx.x;
    const int lane = t & 31, wid = t >> 5;
    const int g = lane >> 2, tg = lane & 3;
    const int wm = (wid & 3) * 32, wn = (wid >> 2) * 64;
    const int m0 = blockIdx.y << 7, n0 = blockIdx.x << 7;
    const int nch = K >> 5;

    const int l15 = lane & 15, lh = lane >> 4;
    const uint32_t sb = smem_u32(smg);
    const uint32_t offA = (uint32_t)((wm + l15) * 80 + lh * 16);
    const uint32_t offB = (uint32_t)((wn + l15) * 80 + lh * 16);

    float d[2][8][4];
#pragma unroll
    for (int i = 0; i < 2; i++)
#pragma unroll
        for (int j = 0; j < 8; j++)
#pragma unroll
            for (int q = 0; q < 4; q++) d[i][j][q] = 0.f;

#define G_ISSUE(c) do { \
    uint32_t base = sb + ((c) & 3) * GSTAGE_B; \
    _Pragma("unroll") \
    for (int j = 0; j < 2; j++) { \
        int u = t + (j << 8); int row = u >> 2, c8 = u & 3; \
        uint32_t dst = base + (uint32_t)(row * GSTRIDE + (c8 << 3)) * 2; \
        size_t ao = (size_t)(m0 + row) * K + ((c) << 5) + (c8 << 3); \
        size_t bo = (size_t)(n0 + row) * K + ((c) << 5) + (c8 << 3); \
        CP16(dst, Ah_g + ao); \
        CP16(dst + GBUF_B, Al_g + ao); \
        CP16(dst + 2 * GBUF_B, Bh_g + bo); \
        CP16(dst + 3 * GBUF_B, Bl_g + bo); \
    } } while (0)

    G_ISSUE(0); CP_COMMIT();
    G_ISSUE(1); CP_COMMIT();
    G_ISSUE(2); CP_COMMIT();

    for (int c = 0; c < nch; c++) {
        CP_WAIT(2);
        __syncthreads();
        if (c + 3 < nch) G_ISSUE(c + 3);
        CP_COMMIT();

        const uint32_t base = sb + (c & 3) * GSTAGE_B;
#pragma unroll
        for (int ks = 0; ks < 2; ks++) {
            const uint32_t ko = ks * 32;
            uint32_t ah[2][4], al[2][4];
#pragma unroll
            for (int mt = 0; mt < 2; mt++) {
                LDSM4(ah[mt], base + offA + mt * 1280 + ko);
                LDSM4(al[mt], base + GBUF_B + offA + mt * 1280 + ko);
            }
#pragma unroll
            for (int jp = 0; jp < 4; jp++) {
                uint32_t bh4[4], bl4[4];
                LDSM4(bh4, base + 2 * GBUF_B + offB + jp * 1280 + ko);
                LDSM4(bl4, base + 3 * GBUF_B + offB + jp * 1280 + ko);
                uint32_t b0h[2] = {bh4[0], bh4[2]}, b1h[2] = {bh4[1], bh4[3]};
                uint32_t b0l[2] = {bl4[0], bl4[2]}, b1l[2] = {bl4[1], bl4[3]};
#pragma unroll
                for (int mt = 0; mt < 2; mt++) {
                    MMA_BF(d[mt][2 * jp], ah[mt], b0h);
                    MMA_BF(d[mt][2 * jp], ah[mt], b0l);
                    MMA_BF(d[mt][2 * jp], al[mt], b0h);
                    MMA_BF(d[mt][2 * jp + 1], ah[mt], b1h);
                    MMA_BF(d[mt][2 * jp + 1], ah[mt], b1l);
                    MMA_BF(d[mt][2 * jp + 1], al[mt], b1h);
                }
            }
        }
    }

    // epilogue
#pragma unroll
    for (int i = 0; i < 2; i++) {
        int r = m0 + wm + i * 16 + g;
#pragma unroll
        for (int j = 0; j < 8; j++) {
            int cix = n0 + wn + j * 8 + tg * 2;
            float2 b2 = *(const float2*)(bias + cix);
            float2 v0, v1;
            v0.x = d[i][j][0] + b2.x; v0.y = d[i][j][1] + b2.y;
            v1.x = d[i][j][2] + b2.x; v1.y = d[i][j][3] + b2.y;
            *(float2*)(C + (size_t)r * N + cix) = v0;
            *(float2*)(C + (size_t)(r + 8) * N + cix) = v1;
        }
    }
#undef G_ISSUE
}

// =================== bf16 flash attention, cp.async double-buffered ==========
// 256 threads (8 warps), CTA = 128 q rows of one head; warp w owns rows
// [16w,16w+16). k-tiles of 64 keys, prefetched with cp.async.
#define APAD 136                       // bf16 elems per smem row (272 B)
#define QBUF_E (128 * APAD)            // 17408 elems
#define KVBUF_E (64 * APAD)            // 8704 elems
#define KVBUF_B (KVBUF_E * 2)          // 17408 bytes
#define KVSTAGE_B (4 * KVBUF_B)        // 69632 bytes
#define ATTN_SMEM (2 * QBUF_E * 2 + 2 * KVSTAGE_B)   // 208896 bytes

__global__ void __launch_bounds__(256, 1) attn_tc() {
    extern __shared__ bf16 sma[];
    bf16* Qh = sma;
    bf16* Ql = sma + QBUF_E;

    const int t = threadIdx.x;
    const int lane = t & 31, w = t >> 5;
    const int g = lane >> 2, tg = lane & 3;
    const int qt = gridDim.x - 1 - blockIdx.x;    // heavy CTAs first
    const int q0 = qt * 128;
    const int h = blockIdx.y, kvh = h >> 2;
    const int wq = w * 16;

    const uint32_t kvb = smem_u32(sma) + 2 * QBUF_E * 2;   // KV stages base (bytes)

#define A_ISSUE(kt) do { \
    uint32_t base = kvb + ((kt) & 1) * KVSTAGE_B; \
    _Pragma("unroll") \
    for (int i = 0; i < 4; i++) { \
        int u = t + (i << 8); int r = u >> 4, cc = u & 15; \
        size_t so = ((size_t)(((kt) << 6) + r) * NKV + kvh) * HD + cc * 8; \
        uint32_t dd = base + (uint32_t)(r * 272 + cc * 16); \
        CP16(dd, g_kh + so); \
        CP16(dd + KVBUF_B, g_kl + so); \
        CP16(dd + 2 * KVBUF_B, g_vh + so); \
        CP16(dd + 3 * KVBUF_B, g_vl + so); \
    } } while (0)

    A_ISSUE(0); CP_COMMIT();

    // ---- stage Q (regular stores; covered by first barrier) ----
#pragma unroll
    for (int i = 0; i < 8; i++) {
        int u = t + i * 256;
        int r = u >> 4, cc = u & 15;
        size_t qo = ((size_t)(q0 + r) * NH + h) * HD + cc * 8;
        *(uint4*)((char*)Qh + r * 272 + cc * 16) = *(const uint4*)(g_qh + qo);
        *(uint4*)((char*)Ql + r * 272 + cc * 16) = *(const uint4*)(g_ql + qo);
    }

    const int l15 = lane & 15, lh = lane >> 4;
    const uint32_t qb_h = smem_u32(Qh) + (wq + l15) * 272 + lh * 16;
    const uint32_t qb_l = qb_h + QBUF_E * 2;
    uint32_t kb[4];
#pragma unroll
    for (int jp = 0; jp < 4; jp++)
        kb[jp] = kvb + (jp * 16 + l15) * 272 + lh * 16;
    const uint32_t vb = kvb + 2 * KVBUF_B + l15 * 272 + lh * 16;

    float o[16][4];
#pragma unroll
    for (int dt = 0; dt < 16; dt++)
#pragma unroll
        for (int q = 0; q < 4; q++) o[dt][q] = 0.f;
    float mrow[2] = {-1e30f, -1e30f};
    float lrow[2] = {0.f, 0.f};

    const int nkt = 2 * (qt + 1);
    for (int kt = 0; kt < nkt; kt++) {
        CP_WAIT(0);
        __syncthreads();
        if (kt + 1 < nkt) { A_ISSUE(kt + 1); CP_COMMIT(); }
        const uint32_t kvo = (kt & 1) * KVSTAGE_B;
        const int k0 = kt * 64;

        // ---- scores S[16q x 64k] (3xBF16 over d=128) ----
        float s[8][4];
#pragma unroll
        for (int j = 0; j < 8; j++)
#pragma unroll
            for (int q = 0; q < 4; q++) s[j][q] = 0.f;

#pragma unroll
        for (int ks = 0; ks < 8; ks++) {
            const uint32_t ko = ks * 32;
            uint32_t aqh[4], aql[4];
            LDSM4(aqh, qb_h + ko);
            LDSM4(aql, qb_l + ko);
#pragma unroll
            for (int jp = 0; jp < 4; jp++) {
                uint32_t kh4[4], kl4[4];
                LDSM4(kh4, kb[jp] + kvo + ko);
                LDSM4(kl4, kb[jp] + kvo + KVBUF_B + ko);
                uint32_t b0h[2] = {kh4[0], kh4[2]}, b1h[2] = {kh4[1], kh4[3]};
                uint32_t b0l[2] = {kl4[0], kl4[2]}, b1l[2] = {kl4[1], kl4[3]};
                MMA_BF(s[2 * jp], aqh, b0h);
                MMA_BF(s[2 * jp], aqh, b0l);
                MMA_BF(s[2 * jp], aql, b0h);
                MMA_BF(s[2 * jp + 1], aqh, b1h);
                MMA_BF(s[2 * jp + 1], aqh, b1l);
                MMA_BF(s[2 * jp + 1], aql, b1h);
            }
        }

        // ---- causal mask (last two tiles only) ----
        if (kt >= nkt - 2) {
            const int rbase = q0 + wq + g;
#pragma unroll
            for (int j = 0; j < 8; j++) {
                int cg = k0 + 8 * j + 2 * tg;
                if (cg > rbase) s[j][0] = -1e9f;
                if (cg + 1 > rbase) s[j][1] = -1e9f;
                if (cg > rbase + 8) s[j][2] = -1e9f;
                if (cg + 1 > rbase + 8) s[j][3] = -1e9f;
            }
        }

        // ---- online softmax ----
#pragma unroll
        for (int rr = 0; rr < 2; rr++) {
            float tmax = -1e30f;
#pragma unroll
            for (int j = 0; j < 8; j++)
                tmax = fmaxf(tmax, fmaxf(s[j][rr * 2], s[j][rr * 2 + 1]));
            tmax = fmaxf(tmax, __shfl_xor_sync(0xffffffffu, tmax, 1));
            tmax = fmaxf(tmax, __shfl_xor_sync(0xffffffffu, tmax, 2));
            float mnew = fmaxf(mrow[rr], tmax);
            float scalef = __expf(mrow[rr] - mnew);
            mrow[rr] = mnew;
            float tsum = 0.f;
#pragma unroll
            for (int j = 0; j < 8; j++) {
                float p0 = __expf(s[j][rr * 2] - mnew);
                float p1 = __expf(s[j][rr * 2 + 1] - mnew);
                s[j][rr * 2] = p0;
                s[j][rr * 2 + 1] = p1;
                tsum += p0 + p1;
            }
            tsum += __shfl_xor_sync(0xffffffffu, tsum, 1);
            tsum += __shfl_xor_sync(0xffffffffu, tsum, 2);
            lrow[rr] = lrow[rr] * scalef + tsum;
#pragma unroll
            for (int dt = 0; dt < 16; dt++) {
                o[dt][rr * 2] *= scalef;
                o[dt][rr * 2 + 1] *= scalef;
            }
        }

        // ---- PV ----
#pragma unroll
        for (int c = 0; c < 4; c++) {
            uint32_t pah[4], pal[4];
#pragma unroll
            for (int hq = 0; hq < 2; hq++) {
                float p0 = s[2 * c + hq][0], p1 = s[2 * c + hq][1];
                float p2 = s[2 * c + hq][2], p3 = s[2 * c + hq][3];
                float h0 = bfhi(p0), h1 = bfhi(p1), h2 = bfhi(p2), h3 = bfhi(p3);
                pah[hq * 2 + 0] = packbf(p0, p1);
                pah[hq * 2 + 1] = packbf(p2, p3);
                pal[hq * 2 + 0] = packbf(p0 - h0, p1 - h1);
                pal[hq * 2 + 1] = packbf(p2 - h2, p3 - h3);
            }
            const uint32_t vrow = vb + kvo + c * (16 * 272);
#pragma unroll
            for (int dt16 = 0; dt16 < 8; dt16++) {
                uint32_t vh4[4], vl4[4];
                LDSM4T(vh4, vrow + dt16 * 32);
                LDSM4T(vl4, vrow + KVBUF_B + dt16 * 32);
                uint32_t bv0h[2] = {vh4[0], vh4[1]}, bv1h[2] = {vh4[2], vh4[3]};
                uint32_t bv0l[2] = {vl4[0], vl4[1]}, bv1l[2] = {vl4[2], vl4[3]};
                MMA_BF(o[2 * dt16], pah, bv0h);
                MMA_BF(o[2 * dt16], pah, bv0l);
                MMA_BF(o[2 * dt16], pal, bv0h);
                MMA_BF(o[2 * dt16 + 1], pah, bv1h);
                MMA_BF(o[2 * dt16 + 1], pah, bv1l);
                MMA_BF(o[2 * dt16 + 1], pal, bv1h);
            }
        }
    }

    // ---- epilogue ----
#pragma unroll
    for (int rr = 0; rr < 2; rr++) {
        float invl = 1.0f / lrow[rr];
        int row = q0 + wq + g + rr * 8;
#pragma unroll
        for (int dt = 0; dt < 16; dt++) {
            float x0 = o[dt][rr * 2] * invl;
            float x1 = o[dt][rr * 2 + 1] * invl;
            float h0 = bfhi(x0), h1 = bfhi(x1);
            size_t off = (size_t)row * (NH * HD) + h * HD + dt * 8 + 2 * tg;
            *(uint32_t*)(g_ah + off) = packbf(x0, x1);
            *(uint32_t*)(g_al + off) = packbf(x0 - h0, x1 - h1);
        }
    }
#undef A_ISSUE
}

// ---------------- launch -----------------------------------------------------
extern "C" void kernel_launch(void* const* d_in, const int* in_sizes, int n_in,
                              void* d_out, int out_size) {
    const float* hidden = (const float*)d_in[0];
    const float* cosb   = (const float*)d_in[1];
    const float* sinb   = (const float*)d_in[2];
    const float* kcache = (const float*)d_in[3];
    const float* vcache = (const float*)d_in[4];
    const float* wqkv   = (const float*)d_in[6];
    const float* bqkv   = (const float*)d_in[7];
    const float* wo     = (const float*)d_in[8];
    const float* bo     = (const float*)d_in[9];
    const float* qw     = (const float*)d_in[10];
    const float* kw     = (const float*)d_in[11];
    const int*   widx   = (const int*)d_in[12];
    float* out = (float*)d_out;

    float* p_qkv;
    bf16 *p_hidh, *p_hidl, *p_wqh, *p_wql, *p_woh, *p_wol, *p_ah, *p_al;
    cudaGetSymbolAddress((void**)&p_qkv, g_qkv);
    cudaGetSymbolAddress((void**)&p_hidh, g_hidh);
    cudaGetSymbolAddress((void**)&p_hidl, g_hidl);
    cudaGetSymbolAddress((void**)&p_wqh, g_wqh);
    cudaGetSymbolAddress((void**)&p_wql, g_wql);
    cudaGetSymbolAddress((void**)&p_woh, g_woh);
    cudaGetSymbolAddress((void**)&p_wol, g_wol);
    cudaGetSymbolAddress((void**)&p_ah, g_ah);
    cudaGetSymbolAddress((void**)&p_al, g_al);

    static bool attr_set = false;
    if (!attr_set) {
        cudaFuncSetAttribute(gemm_bf, cudaFuncAttributeMaxDynamicSharedMemorySize, G_SMEM);
        cudaFuncSetAttribute(attn_tc, cudaFuncAttributeMaxDynamicSharedMemorySize, ATTN_SMEM);
        attr_set = true;
    }

    // 0. split inputs to bf16 hi/lo
    split_bf16k<<<1024, 256>>>(hidden, p_hidh, p_hidl, S_LEN * HID / 4);
    split_bf16k<<<1024, 256>>>(wqkv, p_wqh, p_wql, QKV_OUT * HID / 4);
    split_bf16k<<<1024, 256>>>(wo, p_woh, p_wol, HID * HID / 4);

    // 1. QKV GEMM (3xBF16 + cp.async)
    gemm_bf<<<dim3(QKV_OUT / 128, S_LEN / 128), 256, G_SMEM>>>(
        p_hidh, p_hidl, p_wqh, p_wql, bqkv, p_qkv, QKV_OUT, HID);

    // 2. caches -> split scratch
    copy_caches<<<256, 256>>>(kcache, vcache);

    // 3. RMSNorm + RoPE + scale + scatter
    norm_rope_scatter<<<dim3(S_LEN, 24), 128>>>(cosb, sinb, qw, kw, widx);

    // 4. bf16 flash attention (cp.async double-buffered)
    attn_tc<<<dim3(S_LEN / 128, NH), 256, ATTN_SMEM>>>();

    // 5. output projection (3xBF16 + cp.async)
    gemm_bf<<<dim3(HID / 128, S_LEN / 128), 256, G_SMEM>>>(
        p_ah, p_al, p_woh, p_wol, bo, out, HID, NH * HD);
}

// round 8
// speedup vs baseline: 3.2160x; 1.0003x over previous
#include <cuda_runtime.h>
#include <cuda_bf16.h>
#include <cstdint>
#include <math.h>

// Problem constants
#define S_LEN 2048
#define HID 2048
#define NH 16
#define NKV 4
#define HD 128
#define QKV_OUT 3072
#define Q_SZ 2048
#define KV_SZ 512
#define SCALE_Q 0.08838834764831845f

typedef __nv_bfloat16 bf16;

// ---------------- scratch ----------------------------------------------------
__device__ float g_qkv[S_LEN * QKV_OUT];
__device__ bf16 g_hidh[S_LEN * HID], g_hidl[S_LEN * HID];
__device__ bf16 g_wqh[QKV_OUT * HID], g_wql[QKV_OUT * HID];
__device__ bf16 g_woh[HID * HID], g_wol[HID * HID];
__device__ bf16 g_qh[S_LEN * NH * HD], g_ql[S_LEN * NH * HD];
__device__ bf16 g_kh[S_LEN * NKV * HD], g_kl[S_LEN * NKV * HD];
__device__ bf16 g_vh[S_LEN * NKV * HD], g_vl[S_LEN * NKV * HD];
__device__ bf16 g_ah[S_LEN * NH * HD], g_al[S_LEN * NH * HD];

// ---------------- helpers ----------------------------------------------------
__device__ __forceinline__ uint32_t smem_u32(const void* p) {
    return (uint32_t)__cvta_generic_to_shared(p);
}
__device__ __forceinline__ float bfhi(float x) {
    return __bfloat162float(__float2bfloat16(x));
}
__device__ __forceinline__ uint32_t packbf(float lo_v, float hi_v) {
    uint32_t r;
    asm("cvt.rn.bf16x2.f32 %0, %1, %2;" : "=r"(r) : "f"(hi_v), "f"(lo_v));
    return r;
}

#define MMA_BF(d, a, b) \
    asm volatile( \
        "mma.sync.aligned.m16n8k16.row.col.f32.bf16.bf16.f32 " \
        "{%0,%1,%2,%3}, {%4,%5,%6,%7}, {%8,%9}, {%0,%1,%2,%3};" \
        : "+f"((d)[0]), "+f"((d)[1]), "+f"((d)[2]), "+f"((d)[3]) \
        : "r"((a)[0]), "r"((a)[1]), "r"((a)[2]), "r"((a)[3]), \
          "r"((b)[0]), "r"((b)[1]))

#define MMA_BF2(d, a, b0, b1) \
    asm volatile( \
        "mma.sync.aligned.m16n8k16.row.col.f32.bf16.bf16.f32 " \
        "{%0,%1,%2,%3}, {%4,%5,%6,%7}, {%8,%9}, {%0,%1,%2,%3};" \
        : "+f"((d)[0]), "+f"((d)[1]), "+f"((d)[2]), "+f"((d)[3]) \
        : "r"((a)[0]), "r"((a)[1]), "r"((a)[2]), "r"((a)[3]), \
          "r"(b0), "r"(b1))

#define LDSM4(r, addr) \
    asm volatile("ldmatrix.sync.aligned.m8n8.x4.shared.b16 {%0,%1,%2,%3}, [%4];" \
        : "=r"((r)[0]), "=r"((r)[1]), "=r"((r)[2]), "=r"((r)[3]) : "r"(addr))

#define LDSM4T(r, addr) \
    asm volatile("ldmatrix.sync.aligned.m8n8.x4.trans.shared.b16 {%0,%1,%2,%3}, [%4];" \
        : "=r"((r)[0]), "=r"((r)[1]), "=r"((r)[2]), "=r"((r)[3]) : "r"(addr))

#define CP16(dst, src) \
    asm volatile("cp.async.cg.shared.global [%0], [%1], 16;" :: "r"(dst), "l"(src))
#define CP_COMMIT() asm volatile("cp.async.commit_group;" ::: "memory")
#define CP_WAIT(n) asm volatile("cp.async.wait_group %0;" :: "n"(n) : "memory")

// ---------------- split kernels ---------------------------------------------
__global__ void split_bf16k(const float* __restrict__ src, bf16* __restrict__ hi,
                            bf16* __restrict__ lo, int n4) {
    __nv_bfloat162* H = (__nv_bfloat162*)hi;
    __nv_bfloat162* L = (__nv_bfloat162*)lo;
    for (int i = blockIdx.x * blockDim.x + threadIdx.x; i < n4;
         i += gridDim.x * blockDim.x) {
        float4 v = ((const float4*)src)[i];
        bf16 h0 = __float2bfloat16(v.x), h1 = __float2bfloat16(v.y);
        bf16 h2 = __float2bfloat16(v.z), h3 = __float2bfloat16(v.w);
        bf16 l0 = __float2bfloat16(v.x - __bfloat162float(h0));
        bf16 l1 = __float2bfloat16(v.y - __bfloat162float(h1));
        bf16 l2 = __float2bfloat16(v.z - __bfloat162float(h2));
        bf16 l3 = __float2bfloat16(v.w - __bfloat162float(h3));
        H[2 * i] = __nv_bfloat162(h0, h1);
        H[2 * i + 1] = __nv_bfloat162(h2, h3);
        L[2 * i] = __nv_bfloat162(l0, l1);
        L[2 * i + 1] = __nv_bfloat162(l2, l3);
    }
}

__global__ void copy_caches(const float* __restrict__ kc, const float* __restrict__ vc) {
    int n = S_LEN * NKV * HD;
    for (int i = blockIdx.x * blockDim.x + threadIdx.x; i < n;
         i += gridDim.x * blockDim.x) {
        float k = kc[i], v = vc[i];
        bf16 kh = __float2bfloat16(k);
        bf16 vh = __float2bfloat16(v);
        g_kh[i] = kh; g_kl[i] = __float2bfloat16(k - __bfloat162float(kh));
        g_vh[i] = vh; g_vl[i] = __float2bfloat16(v - __bfloat162float(vh));
    }
}

// ---------------- fused RMSNorm + RoPE + scale + scatter ---------------------
__global__ void norm_rope_scatter(const float* __restrict__ cosb,
                                  const float* __restrict__ sinb,
                                  const float* __restrict__ qw,
                                  const float* __restrict__ kw,
                                  const int* __restrict__ widx) {
    const int s = blockIdx.x;
    const int head = blockIdx.y;
    const int d = threadIdx.x;
    __shared__ float sh[128];
    __shared__ float wsum[4];

    int col;
    if (head < 16)      col = head * HD + d;
    else if (head < 20) col = Q_SZ + (head - 16) * HD + d;
    else                col = Q_SZ + KV_SZ + (head - 20) * HD + d;

    float x = g_qkv[(size_t)s * QKV_OUT + col];

    if (head >= 20) {
        size_t o = ((size_t)widx[s] * NKV + (head - 20)) * HD + d;
        bf16 h = __float2bfloat16(x);
        g_vh[o] = h;
        g_vl[o] = __float2bfloat16(x - __bfloat162float(h));
        return;
    }

    float sq = x * x;
#pragma unroll
    for (int m = 16; m; m >>= 1) sq += __shfl_xor_sync(0xffffffffu, sq, m);
    if ((d & 31) == 0) wsum[d >> 5] = sq;
    __syncthreads();
    float ms = (wsum[0] + wsum[1] + wsum[2] + wsum[3]) * (1.0f / 128.0f);
    float inv = rsqrtf(ms + 1e-6f);
    const float* w = (head < 16) ? qw : kw;
    float y = x * inv * w[d];
    sh[d] = y;
    __syncthreads();

    if (d < 64) {
        float c = cosb[s * 64 + d], sn = sinb[s * 64 + d];
        float x1 = sh[d], x2 = sh[d + 64];
        float y1 = x1 * c - x2 * sn;
        float y2 = x1 * sn + x2 * c;
        if (head < 16) {
            y1 *= SCALE_Q; y2 *= SCALE_Q;
            size_t o = ((size_t)s * NH + head) * HD;
            bf16 h1 = __float2bfloat16(y1), h2 = __float2bfloat16(y2);
            g_qh[o + d] = h1;
            g_ql[o + d] = __float2bfloat16(y1 - __bfloat162float(h1));
            g_qh[o + d + 64] = h2;
            g_ql[o + d + 64] = __float2bfloat16(y2 - __bfloat162float(h2));
        } else {
            size_t o = ((size_t)widx[s] * NKV + (head - 16)) * HD;
            bf16 h1 = __float2bfloat16(y1), h2 = __float2bfloat16(y2);
            g_kh[o + d] = h1;
            g_kl[o + d] = __float2bfloat16(y1 - __bfloat162float(h1));
            g_kh[o + d + 64] = h2;
            g_kl[o + d + 64] = __float2bfloat16(y2 - __bfloat162float(h2));
        }
    }
}

// =================== 3xBF16 GEMM, term-major MMA ordering ====================
#define GSTRIDE 40
#define GBUF_E (128 * GSTRIDE)
#define GBUF_B (GBUF_E * 2)
#define GSTAGE_B (4 * GBUF_B)
#define G_SMEM (4 * GSTAGE_B)             // 163840 bytes

__global__ void __launch_bounds__(256)
gemm_bf(const bf16* __restrict__ Ah_g, const bf16* __restrict__ Al_g,
        const bf16* __restrict__ Bh_g, const bf16* __restrict__ Bl_g,
        const float* __restrict__ bias, float* __restrict__ C,
        int N, int K) {
    extern __shared__ bf16 smg[];
    const int t = threadIdx.x;
    const int lane = t & 31, wid = t >> 5;
    const int g = lane >> 2, tg = lane & 3;
    const int wm = (wid & 3) * 32, wn = (wid >> 2) * 64;
    const int m0 = blockIdx.y << 7, n0 = blockIdx.x << 7;
    const int nch = K >> 5;

    const int l15 = lane & 15, lh = lane >> 4;
    const uint32_t sb = smem_u32(smg);
    const uint32_t offA = (uint32_t)((wm + l15) * 80 + lh * 16);
    const uint32_t offB = (uint32_t)((wn + l15) * 80 + lh * 16);

    float d[2][8][4];
#pragma unroll
    for (int i = 0; i < 2; i++)
#pragma unroll
        for (int j = 0; j < 8; j++)
#pragma unroll
            for (int q = 0; q < 4; q++) d[i][j][q] = 0.f;

#define G_ISSUE(c) do { \
    uint32_t base = sb + ((c) & 3) * GSTAGE_B; \
    _Pragma("unroll") \
    for (int j = 0; j < 2; j++) { \
        int u = t + (j << 8); int row = u >> 2, c8 = u & 3; \
        uint32_t dst = base + (uint32_t)(row * GSTRIDE + (c8 << 3)) * 2; \
        size_t ao = (size_t)(m0 + row) * K + ((c) << 5) + (c8 << 3); \
        size_t bo = (size_t)(n0 + row) * K + ((c) << 5) + (c8 << 3); \
        CP16(dst, Ah_g + ao); \
        CP16(dst + GBUF_B, Al_g + ao); \
        CP16(dst + 2 * GBUF_B, Bh_g + bo); \
        CP16(dst + 3 * GBUF_B, Bl_g + bo); \
    } } while (0)

    G_ISSUE(0); CP_COMMIT();
    G_ISSUE(1); CP_COMMIT();
    G_ISSUE(2); CP_COMMIT();

    for (int c = 0; c < nch; c++) {
        CP_WAIT(2);
        __syncthreads();
        if (c + 3 < nch) G_ISSUE(c + 3);
        CP_COMMIT();

        const uint32_t base = sb + (c & 3) * GSTAGE_B;
#pragma unroll
        for (int ks = 0; ks < 2; ks++) {
            const uint32_t ko = ks * 32;
            uint32_t ah[2][4], al[2][4];
#pragma unroll
            for (int mt = 0; mt < 2; mt++) {
                LDSM4(ah[mt], base + offA + mt * 1280 + ko);
                LDSM4(al[mt], base + GBUF_B + offA + mt * 1280 + ko);
            }
            uint32_t bh4[4][4], bl4[4][4];
#pragma unroll
            for (int jp = 0; jp < 4; jp++) {
                LDSM4(bh4[jp], base + 2 * GBUF_B + offB + jp * 1280 + ko);
                LDSM4(bl4[jp], base + 3 * GBUF_B + offB + jp * 1280 + ko);
            }
            // pass 1: Ah x Bh  (16 independent accumulators)
#pragma unroll
            for (int jp = 0; jp < 4; jp++)
#pragma unroll
                for (int mt = 0; mt < 2; mt++) {
                    MMA_BF2(d[mt][2 * jp], ah[mt], bh4[jp][0], bh4[jp][2]);
                    MMA_BF2(d[mt][2 * jp + 1], ah[mt], bh4[jp][1], bh4[jp][3]);
                }
            // pass 2: Ah x Bl
#pragma unroll
            for (int jp = 0; jp < 4; jp++)
#pragma unroll
                for (int mt = 0; mt < 2; mt++) {
                    MMA_BF2(d[mt][2 * jp], ah[mt], bl4[jp][0], bl4[jp][2]);
                    MMA_BF2(d[mt][2 * jp + 1], ah[mt], bl4[jp][1], bl4[jp][3]);
                }
            // pass 3: Al x Bh
#pragma unroll
            for (int jp = 0; jp < 4; jp++)
#pragma unroll
                for (int mt = 0; mt < 2; mt++) {
                    MMA_BF2(d[mt][2 * jp], al[mt], bh4[jp][0], bh4[jp][2]);
                    MMA_BF2(d[mt][2 * jp + 1], al[mt], bh4[jp][1], bh4[jp][3]);
                }
        }
    }

    // epilogue
#pragma unroll
    for (int i = 0; i < 2; i++) {
        int r = m0 + wm + i * 16 + g;
#pragma unroll
        for (int j = 0; j < 8; j++) {
            int cix = n0 + wn + j * 8 + tg * 2;
            float2 b2 = *(const float2*)(bias + cix);
            float2 v0, v1;
            v0.x = d[i][j][0] + b2.x; v0.y = d[i][j][1] + b2.y;
            v1.x = d[i][j][2] + b2.x; v1.y = d[i][j][3] + b2.y;
            *(float2*)(C + (size_t)r * N + cix) = v0;
            *(float2*)(C + (size_t)(r + 8) * N + cix) = v1;
        }
    }
#undef G_ISSUE
}

// =================== bf16 flash attention, term-major MMA ordering ===========
#define APAD 136
#define QBUF_E (128 * APAD)
#define KVBUF_E (64 * APAD)
#define KVBUF_B (KVBUF_E * 2)
#define KVSTAGE_B (4 * KVBUF_B)
#define ATTN_SMEM (2 * QBUF_E * 2 + 2 * KVSTAGE_B)   // 208896 bytes

__global__ void __launch_bounds__(256, 1) attn_tc() {
    extern __shared__ bf16 sma[];
    bf16* Qh = sma;
    bf16* Ql = sma + QBUF_E;

    const int t = threadIdx.x;
    const int lane = t & 31, w = t >> 5;
    const int g = lane >> 2, tg = lane & 3;
    const int qt = gridDim.x - 1 - blockIdx.x;
    const int q0 = qt * 128;
    const int h = blockIdx.y, kvh = h >> 2;
    const int wq = w * 16;

    const uint32_t kvb = smem_u32(sma) + 2 * QBUF_E * 2;

#define A_ISSUE(kt) do { \
    uint32_t base = kvb + ((kt) & 1) * KVSTAGE_B; \
    _Pragma("unroll") \
    for (int i = 0; i < 4; i++) { \
        int u = t + (i << 8); int r = u >> 4, cc = u & 15; \
        size_t so = ((size_t)(((kt) << 6) + r) * NKV + kvh) * HD + cc * 8; \
        uint32_t dd = base + (uint32_t)(r * 272 + cc * 16); \
        CP16(dd, g_kh + so); \
        CP16(dd + KVBUF_B, g_kl + so); \
        CP16(dd + 2 * KVBUF_B, g_vh + so); \
        CP16(dd + 3 * KVBUF_B, g_vl + so); \
    } } while (0)

    A_ISSUE(0); CP_COMMIT();

#pragma unroll
    for (int i = 0; i < 8; i++) {
        int u = t + i * 256;
        int r = u >> 4, cc = u & 15;
        size_t qo = ((size_t)(q0 + r) * NH + h) * HD + cc * 8;
        *(uint4*)((char*)Qh + r * 272 + cc * 16) = *(const uint4*)(g_qh + qo);
        *(uint4*)((char*)Ql + r * 272 + cc * 16) = *(const uint4*)(g_ql + qo);
    }

    const int l15 = lane & 15, lh = lane >> 4;
    const uint32_t qb_h = smem_u32(Qh) + (wq + l15) * 272 + lh * 16;
    const uint32_t qb_l = qb_h + QBUF_E * 2;
    uint32_t kb[4];
#pragma unroll
    for (int jp = 0; jp < 4; jp++)
        kb[jp] = kvb + (jp * 16 + l15) * 272 + lh * 16;
    const uint32_t vb = kvb + 2 * KVBUF_B + l15 * 272 + lh * 16;

    float o[16][4];
#pragma unroll
    for (int dt = 0; dt < 16; dt++)
#pragma unroll
        for (int q = 0; q < 4; q++) o[dt][q] = 0.f;
    float mrow[2] = {-1e30f, -1e30f};
    float lrow[2] = {0.f, 0.f};

    const int nkt = 2 * (qt + 1);
    for (int kt = 0; kt < nkt; kt++) {
        CP_WAIT(0);
        __syncthreads();
        if (kt + 1 < nkt) { A_ISSUE(kt + 1); CP_COMMIT(); }
        const uint32_t kvo = (kt & 1) * KVSTAGE_B;
        const int k0 = kt * 64;

        // ---- scores (term-major per ks) ----
        float s[8][4];
#pragma unroll
        for (int j = 0; j < 8; j++)
#pragma unroll
            for (int q = 0; q < 4; q++) s[j][q] = 0.f;

#pragma unroll
        for (int ks = 0; ks < 8; ks++) {
            const uint32_t ko = ks * 32;
            uint32_t aqh[4], aql[4];
            LDSM4(aqh, qb_h + ko);
            LDSM4(aql, qb_l + ko);
            uint32_t kh4[4][4], kl4[4][4];
#pragma unroll
            for (int jp = 0; jp < 4; jp++) {
                LDSM4(kh4[jp], kb[jp] + kvo + ko);
                LDSM4(kl4[jp], kb[jp] + kvo + KVBUF_B + ko);
            }
#pragma unroll
            for (int jp = 0; jp < 4; jp++) {
                MMA_BF2(s[2 * jp], aqh, kh4[jp][0], kh4[jp][2]);
                MMA_BF2(s[2 * jp + 1], aqh, kh4[jp][1], kh4[jp][3]);
            }
#pragma unroll
            for (int jp = 0; jp < 4; jp++) {
                MMA_BF2(s[2 * jp], aqh, kl4[jp][0], kl4[jp][2]);
                MMA_BF2(s[2 * jp + 1], aqh, kl4[jp][1], kl4[jp][3]);
            }
#pragma unroll
            for (int jp = 0; jp < 4; jp++) {
                MMA_BF2(s[2 * jp], aql, kh4[jp][0], kh4[jp][2]);
                MMA_BF2(s[2 * jp + 1], aql, kh4[jp][1], kh4[jp][3]);
            }
        }

        // ---- causal mask (last two tiles) ----
        if (kt >= nkt - 2) {
            const int rbase = q0 + wq + g;
#pragma unroll
            for (int j = 0; j < 8; j++) {
                int cg = k0 + 8 * j + 2 * tg;
                if (cg > rbase) s[j][0] = -1e9f;
                if (cg + 1 > rbase) s[j][1] = -1e9f;
                if (cg > rbase + 8) s[j][2] = -1e9f;
                if (cg + 1 > rbase + 8) s[j][3] = -1e9f;
            }
        }

        // ---- online softmax ----
#pragma unroll
        for (int rr = 0; rr < 2; rr++) {
            float tmax = -1e30f;
#pragma unroll
            for (int j = 0; j < 8; j++)
                tmax = fmaxf(tmax, fmaxf(s[j][rr * 2], s[j][rr * 2 + 1]));
            tmax = fmaxf(tmax, __shfl_xor_sync(0xffffffffu, tmax, 1));
            tmax = fmaxf(tmax, __shfl_xor_sync(0xffffffffu, tmax, 2));
            float mnew = fmaxf(mrow[rr], tmax);
            float scalef = __expf(mrow[rr] - mnew);
            mrow[rr] = mnew;
            float tsum = 0.f;
#pragma unroll
            for (int j = 0; j < 8; j++) {
                float p0 = __expf(s[j][rr * 2] - mnew);
                float p1 = __expf(s[j][rr * 2 + 1] - mnew);
                s[j][rr * 2] = p0;
                s[j][rr * 2 + 1] = p1;
                tsum += p0 + p1;
            }
            tsum += __shfl_xor_sync(0xffffffffu, tsum, 1);
            tsum += __shfl_xor_sync(0xffffffffu, tsum, 2);
            lrow[rr] = lrow[rr] * scalef + tsum;
#pragma unroll
            for (int dt = 0; dt < 16; dt++) {
                o[dt][rr * 2] *= scalef;
                o[dt][rr * 2 + 1] *= scalef;
            }
        }

        // ---- PV (term-major per c; V-hi fragments cached across passes) ----
#pragma unroll
        for (int c = 0; c < 4; c++) {
            uint32_t pah[4], pal[4];
#pragma unroll
            for (int hq = 0; hq < 2; hq++) {
                float p0 = s[2 * c + hq][0], p1 = s[2 * c + hq][1];
                float p2 = s[2 * c + hq][2], p3 = s[2 * c + hq][3];
                float h0 = bfhi(p0), h1 = bfhi(p1), h2 = bfhi(p2), h3 = bfhi(p3);
                pah[hq * 2 + 0] = packbf(p0, p1);
                pah[hq * 2 + 1] = packbf(p2, p3);
                pal[hq * 2 + 0] = packbf(p0 - h0, p1 - h1);
                pal[hq * 2 + 1] = packbf(p2 - h2, p3 - h3);
            }
            const uint32_t vrow = vb + kvo + c * (16 * 272);
            uint32_t vh4[8][4];
            // pass 1: Ph x Vh (load + cache Vh fragments)
#pragma unroll
            for (int dt16 = 0; dt16 < 8; dt16++) {
                LDSM4T(vh4[dt16], vrow + dt16 * 32);
                MMA_BF2(o[2 * dt16], pah, vh4[dt16][0], vh4[dt16][1]);
                MMA_BF2(o[2 * dt16 + 1], pah, vh4[dt16][2], vh4[dt16][3]);
            }
            // pass 2: Ph x Vl
#pragma unroll
            for (int dt16 = 0; dt16 < 8; dt16++) {
                uint32_t vl4[4];
                LDSM4T(vl4, vrow + KVBUF_B + dt16 * 32);
                MMA_BF2(o[2 * dt16], pah, vl4[0], vl4[1]);
                MMA_BF2(o[2 * dt16 + 1], pah, vl4[2], vl4[3]);
            }
            // pass 3: Pl x Vh (cached fragments)
#pragma unroll
            for (int dt16 = 0; dt16 < 8; dt16++) {
                MMA_BF2(o[2 * dt16], pal, vh4[dt16][0], vh4[dt16][1]);
                MMA_BF2(o[2 * dt16 + 1], pal, vh4[dt16][2], vh4[dt16][3]);
            }
        }
    }

    // ---- epilogue ----
#pragma unroll
    for (int rr = 0; rr < 2; rr++) {
        float invl = 1.0f / lrow[rr];
        int row = q0 + wq + g + rr * 8;
#pragma unroll
        for (int dt = 0; dt < 16; dt++) {
            float x0 = o[dt][rr * 2] * invl;
            float x1 = o[dt][rr * 2 + 1] * invl;
            float h0 = bfhi(x0), h1 = bfhi(x1);
            size_t off = (size_t)row * (NH * HD) + h * HD + dt * 8 + 2 * tg;
            *(uint32_t*)(g_ah + off) = packbf(x0, x1);
            *(uint32_t*)(g_al + off) = packbf(x0 - h0, x1 - h1);
        }
    }
#undef A_ISSUE
}

// ---------------- launch -----------------------------------------------------
extern "C" void kernel_launch(void* const* d_in, const int* in_sizes, int n_in,
                              void* d_out, int out_size) {
    const float* hidden = (const float*)d_in[0];
    const float* cosb   = (const float*)d_in[1];
    const float* sinb   = (const float*)d_in[2];
    const float* kcache = (const float*)d_in[3];
    const float* vcache = (const float*)d_in[4];
    const float* wqkv   = (const float*)d_in[6];
    const float* bqkv   = (const float*)d_in[7];
    const float* wo     = (const float*)d_in[8];
    const float* bo     = (const float*)d_in[9];
    const float* qw     = (const float*)d_in[10];
    const float* kw     = (const float*)d_in[11];
    const int*   widx   = (const int*)d_in[12];
    float* out = (float*)d_out;

    float* p_qkv;
    bf16 *p_hidh, *p_hidl, *p_wqh, *p_wql, *p_woh, *p_wol, *p_ah, *p_al;
    cudaGetSymbolAddress((void**)&p_qkv, g_qkv);
    cudaGetSymbolAddress((void**)&p_hidh, g_hidh);
    cudaGetSymbolAddress((void**)&p_hidl, g_hidl);
    cudaGetSymbolAddress((void**)&p_wqh, g_wqh);
    cudaGetSymbolAddress((void**)&p_wql, g_wql);
    cudaGetSymbolAddress((void**)&p_woh, g_woh);
    cudaGetSymbolAddress((void**)&p_wol, g_wol);
    cudaGetSymbolAddress((void**)&p_ah, g_ah);
    cudaGetSymbolAddress((void**)&p_al, g_al);

    static bool attr_set = false;
    if (!attr_set) {
        cudaFuncSetAttribute(gemm_bf, cudaFuncAttributeMaxDynamicSharedMemorySize, G_SMEM);
        cudaFuncSetAttribute(attn_tc, cudaFuncAttributeMaxDynamicSharedMemorySize, ATTN_SMEM);
        attr_set = true;
    }

    split_bf16k<<<1024, 256>>>(hidden, p_hidh, p_hidl, S_LEN * HID / 4);
    split_bf16k<<<1024, 256>>>(wqkv, p_wqh, p_wql, QKV_OUT * HID / 4);
    split_bf16k<<<1024, 256>>>(wo, p_woh, p_wol, HID * HID / 4);

    gemm_bf<<<dim3(QKV_OUT / 128, S_LEN / 128), 256, G_SMEM>>>(
        p_hidh, p_hidl, p_wqh, p_wql, bqkv, p_qkv, QKV_OUT, HID);

    copy_caches<<<256, 256>>>(kcache, vcache);

    norm_rope_scatter<<<dim3(S_LEN, 24), 128>>>(cosb, sinb, qw, kw, widx);

    attn_tc<<<dim3(S_LEN / 128, NH), 256, ATTN_SMEM>>>();

    gemm_bf<<<dim3(HID / 128, S_LEN / 128), 256, G_SMEM>>>(
        p_ah, p_al, p_woh, p_wol, bo, out, HID, NH * HD);
}